// round 4
// baseline (speedup 1.0000x reference)
#include <cuda_runtime.h>

// Problem constants
#define NPATCH   32768      // 128 batch * 16*16 patches
#define DDIM     256        // 16 channels * 4*4 patch
#define KCODES   1024
// 1/(2*variance) where variance = -(256 / (2*ln 0.1))  =>  inv2var = ln(10)/256
#define INV2VAR  0.0089944730195076785f

typedef unsigned long long u64;

// Scratch (static device globals; no allocation at runtime)
__device__ float g_patch[NPATCH * DDIM];     // 33.5 MB patchified x
__device__ float g_xnorm[NPATCH];
__device__ float g_cnorm[KCODES];
__device__ float g_smooth[KCODES * DDIM];    // Gaussian-smoothed codebook
__device__ int   g_bmu[NPATCH];

__device__ __forceinline__ void ffma2(u64& d, u64 a, u64 b) {
    asm("fma.rn.f32x2 %0, %1, %2, %0;" : "+l"(d) : "l"(a), "l"(b));
}
__device__ __forceinline__ void unpack2(float& lo, float& hi, u64 v) {
    asm("mov.b64 {%0,%1}, %2;" : "=f"(lo), "=f"(hi) : "l"(v));
}

// ---------------------------------------------------------------------------
// K0: patchify fused with per-patch squared norm.
// Block = 64 threads = one patch (16 channels x 4 py rows, float4 over px).
// ---------------------------------------------------------------------------
__global__ void k_patchify(const float* __restrict__ x) {
    __shared__ float red[2];
    int i = blockIdx.x;
    int t = threadIdx.x;            // 0..63
    int n = i >> 8, rem = i & 255;
    int ph = rem >> 4, pw = rem & 15;
    int c = t >> 2, py = t & 3;
    float4 v = *(const float4*)&x[(((n * 16 + c) * 64 + ph * 4 + py) * 64 + pw * 4)];
    *(float4*)&g_patch[i * DDIM + c * 16 + py * 4] = v;
    float s = fmaf(v.x, v.x, fmaf(v.y, v.y, fmaf(v.z, v.z, v.w * v.w)));
    #pragma unroll
    for (int o = 16; o; o >>= 1) s += __shfl_xor_sync(0xffffffffu, s, o);
    if ((t & 31) == 0) red[t >> 5] = s;
    __syncthreads();
    if (t == 0) g_xnorm[i] = red[0] + red[1];
}

// ---------------------------------------------------------------------------
// K1a: per-code squared norms (one warp per row)
// ---------------------------------------------------------------------------
__global__ void k_cnorm(const float* __restrict__ cb) {
    int row  = blockIdx.x * 8 + (threadIdx.x >> 5);
    int lane = threadIdx.x & 31;
    const float* p = cb + row * DDIM;
    float s = 0.0f;
    #pragma unroll
    for (int j = 0; j < DDIM / 32; ++j) {
        float v = p[lane + j * 32];
        s = fmaf(v, v, s);
    }
    #pragma unroll
    for (int o = 16; o; o >>= 1) s += __shfl_xor_sync(0xffffffffu, s, o);
    if (lane == 0) g_cnorm[row] = s;
}

// ---------------------------------------------------------------------------
// K1b: Gaussian-smoothed codebook. 4 rows per block, 256 blocks.
// smoothed[j][d] = sum_k exp(-(k-j)^2 * INV2VAR) * cb[k][d]
// (truncated at |k-j| > ~64 where weights < 1e-16)
// ---------------------------------------------------------------------------
__global__ void k_smooth(const float* __restrict__ cb) {
    __shared__ float wd[136];       // delta in [-67, 67] -> index delta+67
    int jbase = blockIdx.x * 4;
    int tid = threadIdx.x;
    if (tid < 136) {
        float dd = (float)(tid - 67);
        wd[tid] = expf(-(dd * dd) * INV2VAR);
    }
    __syncthreads();

    float acc[4] = {0.f, 0.f, 0.f, 0.f};
    int klo = jbase - 64;      if (klo < 0) klo = 0;
    int khi = jbase + 3 + 64;  if (khi > KCODES - 1) khi = KCODES - 1;

    for (int kk = klo; kk <= khi; ++kk) {
        float v = cb[kk * DDIM + tid];
        int base = kk - jbase + 67;         // weight idx for t=0
        #pragma unroll
        for (int t = 0; t < 4; ++t)
            acc[t] = fmaf(wd[base - t], v, acc[t]);
    }
    #pragma unroll
    for (int t = 0; t < 4; ++t)
        g_smooth[(jbase + t) * DDIM + tid] = acc[t];
}

// ---------------------------------------------------------------------------
// K2: fused distance GEMM + argmin, packed f32x2 FMA (2 FMAs / instr).
// Block: 128 patches x 128-code chunks (x8 chunks), 256 threads, 8x8 tiles.
// Dims paired (k, k+1) into 64-bit lanes; acc.lo = even-k sum, acc.hi = odd-k.
// Smem double-buffered: one bar.sync per 8-dim slab, global load overlapped.
// d2 = fl( fl(xnorm - 2*s) + cnorm ), first-index tie-break (matches ref).
// ---------------------------------------------------------------------------
__launch_bounds__(256, 1)
__global__ void k_argmin(const float* __restrict__ cb) {
    __shared__ u64 Xs[2][4][128];   // [buf][pair-within-slab][row]
    __shared__ u64 Cs[2][4][128];
    __shared__ float xn_sh[128];
    __shared__ float cn_sh[128];
    __shared__ float bestv[128];
    __shared__ int   besti[128];

    int tid = threadIdx.x;
    int m0  = blockIdx.x * 128;
    int tr  = tid >> 4;        // 0..15 : row group (8 rows each)
    int tc  = tid & 15;        // 0..15 : col group (8 cols each)
    int mrow = tid >> 1;       // 0..127 : load row
    int q    = tid & 1;        // which half of the 8-dim slab

    if (tid < 128) {
        xn_sh[tid] = g_xnorm[m0 + tid];
        bestv[tid] = __int_as_float(0x7f800000);  // +inf
        besti[tid] = 0x7fffffff;
    }

    const float* xrow = &g_patch[(m0 + mrow) * DDIM + q * 4];

    for (int nch = 0; nch < 8; ++nch) {
        __syncthreads();   // protects cn_sh / bestv / smem across chunk boundary
        int n0 = nch << 7;
        if (tid < 128) cn_sh[tid] = g_cnorm[n0 + tid];
        const float* crow = &cb[(n0 + mrow) * DDIM + q * 4];

        u64 acc2[64];
        #pragma unroll
        for (int z = 0; z < 64; ++z) acc2[z] = 0ull;

        union { float4 f; u64 u[2]; } xa, ca;
        xa.f = *(const float4*)&xrow[0];
        ca.f = *(const float4*)&crow[0];

        int cur = 0;
        for (int s = 0; s < 32; ++s) {
            Xs[cur][q * 2 + 0][mrow] = xa.u[0];
            Xs[cur][q * 2 + 1][mrow] = xa.u[1];
            Cs[cur][q * 2 + 0][mrow] = ca.u[0];
            Cs[cur][q * 2 + 1][mrow] = ca.u[1];
            __syncthreads();
            if (s < 31) {   // prefetch next slab; latency hides under compute
                xa.f = *(const float4*)&xrow[(s + 1) * 8];
                ca.f = *(const float4*)&crow[(s + 1) * 8];
            }
            #pragma unroll
            for (int kk = 0; kk < 4; ++kk) {
                u64 a2[8], b2[8];
                ulonglong2 t0, t1, t2, t3;
                t0 = *(const ulonglong2*)&Xs[cur][kk][tr * 8 + 0];
                t1 = *(const ulonglong2*)&Xs[cur][kk][tr * 8 + 2];
                t2 = *(const ulonglong2*)&Xs[cur][kk][tr * 8 + 4];
                t3 = *(const ulonglong2*)&Xs[cur][kk][tr * 8 + 6];
                a2[0]=t0.x; a2[1]=t0.y; a2[2]=t1.x; a2[3]=t1.y;
                a2[4]=t2.x; a2[5]=t2.y; a2[6]=t3.x; a2[7]=t3.y;
                t0 = *(const ulonglong2*)&Cs[cur][kk][tc * 8 + 0];
                t1 = *(const ulonglong2*)&Cs[cur][kk][tc * 8 + 2];
                t2 = *(const ulonglong2*)&Cs[cur][kk][tc * 8 + 4];
                t3 = *(const ulonglong2*)&Cs[cur][kk][tc * 8 + 6];
                b2[0]=t0.x; b2[1]=t0.y; b2[2]=t1.x; b2[3]=t1.y;
                b2[4]=t2.x; b2[5]=t2.y; b2[6]=t3.x; b2[7]=t3.y;
                #pragma unroll
                for (int r = 0; r < 8; ++r)
                    #pragma unroll
                    for (int j = 0; j < 8; ++j)
                        ffma2(acc2[r * 8 + j], a2[r], b2[j]);
            }
            cur ^= 1;
        }

        // Epilogue: d2 + argmin reduce
        #pragma unroll
        for (int r = 0; r < 8; ++r) {
            float xnr = xn_sh[tr * 8 + r];
            float bv = __int_as_float(0x7f800000);
            int   bi = 0x7fffffff;
            #pragma unroll
            for (int j = 0; j < 8; ++j) {
                int code = n0 + tc * 8 + j;
                float lo, hi;
                unpack2(lo, hi, acc2[r * 8 + j]);
                float sdot = lo + hi;
                // fl( fl(xn - 2*s) + cn )  — same rounding chain as reference
                float t = __fmaf_rn(-2.0f, sdot, xnr);
                float v = __fadd_rn(t, cn_sh[tc * 8 + j]);
                if (v < bv || (v == bv && code < bi)) { bv = v; bi = code; }
            }
            // reduce across the 16 threads sharing this row
            #pragma unroll
            for (int o = 1; o < 16; o <<= 1) {
                float ov = __shfl_xor_sync(0xffffffffu, bv, o, 16);
                int   oi = __shfl_xor_sync(0xffffffffu, bi, o, 16);
                if (ov < bv || (ov == bv && oi < bi)) { bv = ov; bi = oi; }
            }
            if (tc == 0) {
                int row = tr * 8 + r;
                if (bv < bestv[row] || (bv == bestv[row] && bi < besti[row])) {
                    bestv[row] = bv; besti[row] = bi;
                }
            }
        }
    }
    __syncthreads();
    if (tid < 128) g_bmu[m0 + tid] = besti[tid];
}

// ---------------------------------------------------------------------------
// K3: gather smoothed[bmu] and un-patchify directly into the output layout
// ---------------------------------------------------------------------------
__global__ void k_output(float* __restrict__ out) {
    int idx = blockIdx.x * blockDim.x + threadIdx.x;
    int w = idx & 63;
    int h = (idx >> 6) & 63;
    int c = (idx >> 12) & 15;
    int n = idx >> 16;
    int i = (n << 8) + ((h >> 2) << 4) + (w >> 2);
    int d = (c << 4) + ((h & 3) << 2) + (w & 3);
    out[idx] = g_smooth[g_bmu[i] * DDIM + d];
}

// ---------------------------------------------------------------------------
extern "C" void kernel_launch(void* const* d_in, const int* in_sizes, int n_in,
                              void* d_out, int out_size) {
    const float* x  = (const float*)d_in[0];   // (128,16,64,64)
    const float* cb = (const float*)d_in[1];   // (1024,256)
    float* out = (float*)d_out;

    k_patchify<<<NPATCH, 64>>>(x);
    k_cnorm  <<<KCODES / 8, 256>>>(cb);
    k_smooth <<<KCODES / 4, 256>>>(cb);
    k_argmin <<<NPATCH / 128, 256>>>(cb);
    k_output <<<NPATCH * DDIM / 256, 256>>>(out);
}

// round 6
// speedup vs baseline: 2.2973x; 2.2973x over previous
#include <cuda_runtime.h>
#include <cuda_bf16.h>
#include <cstdint>

// Problem constants
#define NPATCH   32768      // 128 batch * 16*16 patches
#define DDIM     256        // 16 channels * 4*4 patch
#define KCODES   1024
// 1/(2*variance) where variance = -(256 / (2*ln 0.1))  =>  inv2var = ln(10)/256
#define INV2VAR  0.0089944730195076785f
#define SLOTS    28
#define THRESH   4e-3f

// Scratch (static device globals; no runtime allocation)
__device__ float          g_patch [NPATCH * DDIM];   // fp32 patchified x (rescore)
__device__ __nv_bfloat16  g_patch16[NPATCH * DDIM];  // bf16 copy (tensor prune)
__device__ __nv_bfloat16  g_cb16  [KCODES * DDIM];
__device__ float          g_xnorm [NPATCH];
__device__ float          g_cnorm [KCODES];
__device__ float          g_smooth[KCODES * DDIM];
__device__ short          g_cand  [NPATCH * SLOTS];
__device__ int            g_ccnt  [NPATCH];
__device__ int            g_bmu   [NPATCH];

// ---- monotone float<->uint encoding for atomicMin over floats -------------
__device__ __forceinline__ unsigned encf(float f) {
    unsigned u = __float_as_uint(f);
    return (u & 0x80000000u) ? ~u : (u | 0x80000000u);
}
__device__ __forceinline__ float decf(unsigned u) {
    u = (u & 0x80000000u) ? (u & 0x7fffffffu) : ~u;
    return __uint_as_float(u);
}

// ---- tensor-core primitives ----------------------------------------------
__device__ __forceinline__ void ldsm_x4(uint32_t (&r)[4], uint32_t saddr) {
    asm volatile("ldmatrix.sync.aligned.m8n8.x4.shared.b16 {%0,%1,%2,%3}, [%4];"
                 : "=r"(r[0]), "=r"(r[1]), "=r"(r[2]), "=r"(r[3]) : "r"(saddr));
}
__device__ __forceinline__ void mma_bf16(float (&d)[4], const uint32_t (&a)[4],
                                         uint32_t b0, uint32_t b1) {
    asm volatile("mma.sync.aligned.m16n8k16.row.col.f32.bf16.bf16.f32 "
                 "{%0,%1,%2,%3}, {%4,%5,%6,%7}, {%8,%9}, {%0,%1,%2,%3};"
                 : "+f"(d[0]), "+f"(d[1]), "+f"(d[2]), "+f"(d[3])
                 : "r"(a[0]), "r"(a[1]), "r"(a[2]), "r"(a[3]), "r"(b0), "r"(b1));
}

// ---------------------------------------------------------------------------
// K0: patchify + per-patch norm + bf16 copy. Block = 64 threads = one patch.
// ---------------------------------------------------------------------------
__global__ void k_patchify(const float* __restrict__ x) {
    __shared__ float red[2];
    int i = blockIdx.x;
    int t = threadIdx.x;            // 0..63
    int n = i >> 8, rem = i & 255;
    int ph = rem >> 4, pw = rem & 15;
    int c = t >> 2, py = t & 3;
    float4 v = *(const float4*)&x[(((n * 16 + c) * 64 + ph * 4 + py) * 64 + pw * 4)];
    int dst = i * DDIM + c * 16 + py * 4;
    *(float4*)&g_patch[dst] = v;
    __nv_bfloat162 b01 = __floats2bfloat162_rn(v.x, v.y);
    __nv_bfloat162 b23 = __floats2bfloat162_rn(v.z, v.w);
    *(__nv_bfloat162*)&g_patch16[dst]     = b01;
    *(__nv_bfloat162*)&g_patch16[dst + 2] = b23;
    float s = fmaf(v.x, v.x, fmaf(v.y, v.y, fmaf(v.z, v.z, v.w * v.w)));
    #pragma unroll
    for (int o = 16; o; o >>= 1) s += __shfl_xor_sync(0xffffffffu, s, o);
    if ((t & 31) == 0) red[t >> 5] = s;
    __syncthreads();
    if (t == 0) g_xnorm[i] = red[0] + red[1];
}

// ---------------------------------------------------------------------------
// K1a: per-code squared norms + bf16 codebook copy (one warp per row)
// ---------------------------------------------------------------------------
__global__ void k_cnorm(const float* __restrict__ cb) {
    int row  = blockIdx.x * 8 + (threadIdx.x >> 5);
    int lane = threadIdx.x & 31;
    const float* p = cb + row * DDIM;
    float s = 0.0f;
    #pragma unroll
    for (int j = 0; j < DDIM / 32; ++j) {
        float v = p[lane + j * 32];
        g_cb16[row * DDIM + lane + j * 32] = __float2bfloat16(v);
        s = fmaf(v, v, s);
    }
    #pragma unroll
    for (int o = 16; o; o >>= 1) s += __shfl_xor_sync(0xffffffffu, s, o);
    if (lane == 0) g_cnorm[row] = s;
}

// ---------------------------------------------------------------------------
// K1b: Gaussian-smoothed codebook (radius-64 truncation, weights <1e-16 dropped)
// ---------------------------------------------------------------------------
__global__ void k_smooth(const float* __restrict__ cb) {
    __shared__ float wd[136];
    int jbase = blockIdx.x * 4;
    int tid = threadIdx.x;
    if (tid < 136) {
        float dd = (float)(tid - 67);
        wd[tid] = expf(-(dd * dd) * INV2VAR);
    }
    __syncthreads();
    float acc[4] = {0.f, 0.f, 0.f, 0.f};
    int klo = jbase - 64;      if (klo < 0) klo = 0;
    int khi = jbase + 3 + 64;  if (khi > KCODES - 1) khi = KCODES - 1;
    for (int kk = klo; kk <= khi; ++kk) {
        float v = cb[kk * DDIM + tid];
        int base = kk - jbase + 67;
        #pragma unroll
        for (int t = 0; t < 4; ++t)
            acc[t] = fmaf(wd[base - t], v, acc[t]);
    }
    #pragma unroll
    for (int t = 0; t < 4; ++t)
        g_smooth[(jbase + t) * DDIM + tid] = acc[t];
}

// ---------------------------------------------------------------------------
// K2 (Phase A): bf16 tensor-core prune.
// Block: 128 rows x 1024 codes (8 chunks of 128), 8 warps, warp tile 32x64.
// key = cnorm - 2*(x.c)_bf16 ; per-row running min in shared (atomicMin on
// monotone-encoded floats); collect codes with key <= runmin + THRESH.
// Winner provably collected: |key_bf16 - key_exact| << THRESH/2.
// ---------------------------------------------------------------------------
__global__ __launch_bounds__(256) void k_prune() {
    __shared__ __align__(16) __nv_bfloat16 Xs[128 * 40];  // pad 32->40: LDSM conflict-free
    __shared__ __align__(16) __nv_bfloat16 Cs[128 * 40];
    __shared__ float    cn_sh[128];
    __shared__ unsigned smin[128];
    __shared__ int      cnt[128];
    __shared__ short    slots[128 * SLOTS];

    int tid  = threadIdx.x;
    int lane = tid & 31;
    int wid  = tid >> 5;
    int wm   = wid & 3;            // m band: 32 rows
    int wn   = wid >> 2;           // n band: 64 codes
    int m0   = blockIdx.x * 128;

    if (tid < 128) { smin[tid] = 0xffffffffu; cnt[tid] = 0; }

    uint32_t xs_base = (uint32_t)__cvta_generic_to_shared(Xs);
    uint32_t cs_base = (uint32_t)__cvta_generic_to_shared(Cs);

    // per-thread global-load pattern: 2 x 16B chunks (8 bf16 each)
    int r0c = (tid) >> 2,        g0c = (tid) & 3;
    int r1c = (tid + 256) >> 2,  g1c = (tid + 256) & 3;

    uint4 px0, px1, pc0, pc1;
    auto glob_load = [&](int ls) {
        int k0 = (ls & 7) * 32;
        int n0 = (ls >> 3) << 7;
        px0 = *(const uint4*)&g_patch16[(m0 + r0c) * DDIM + k0 + g0c * 8];
        px1 = *(const uint4*)&g_patch16[(m0 + r1c) * DDIM + k0 + g1c * 8];
        pc0 = *(const uint4*)&g_cb16  [(n0 + r0c) * DDIM + k0 + g0c * 8];
        pc1 = *(const uint4*)&g_cb16  [(n0 + r1c) * DDIM + k0 + g1c * 8];
    };

    float acc[2][8][4];
    glob_load(0);

    for (int ls = 0; ls < 64; ++ls) {
        int s = ls & 7;
        int nchunk0 = (ls >> 3) << 7;
        __syncthreads();                       // prev compute / epilogue done
        *(uint4*)&Xs[r0c * 40 + g0c * 8] = px0;
        *(uint4*)&Xs[r1c * 40 + g1c * 8] = px1;
        *(uint4*)&Cs[r0c * 40 + g0c * 8] = pc0;
        *(uint4*)&Cs[r1c * 40 + g1c * 8] = pc1;
        if (s == 0) {
            if (tid < 128) cn_sh[tid] = g_cnorm[nchunk0 + tid];
            #pragma unroll
            for (int mt = 0; mt < 2; ++mt)
                #pragma unroll
                for (int nt = 0; nt < 8; ++nt)
                    #pragma unroll
                    for (int z = 0; z < 4; ++z) acc[mt][nt][z] = 0.0f;
        }
        __syncthreads();
        if (ls < 63) glob_load(ls + 1);        // prefetch next slab

        #pragma unroll
        for (int kstep = 0; kstep < 2; ++kstep) {
            uint32_t a[2][4];
            #pragma unroll
            for (int mt = 0; mt < 2; ++mt) {
                int row = wm * 32 + mt * 16 + (lane & 15);
                ldsm_x4(a[mt], xs_base + (uint32_t)((row * 40 + kstep * 16 + (lane >> 4) * 8) * 2));
            }
            #pragma unroll
            for (int ntp = 0; ntp < 4; ++ntp) {
                uint32_t b[4];
                int row = wn * 64 + ntp * 16 + (lane & 15);
                ldsm_x4(b, cs_base + (uint32_t)((row * 40 + kstep * 16 + (lane >> 4) * 8) * 2));
                #pragma unroll
                for (int mt = 0; mt < 2; ++mt) {
                    mma_bf16(acc[mt][2 * ntp + 0], a[mt], b[0], b[2]);
                    mma_bf16(acc[mt][2 * ntp + 1], a[mt], b[1], b[3]);
                }
            }
        }

        if (s == 7) {
            // ---- chunk epilogue: keys, running min, candidate collection ----
            // value acc[mt][nt][2h+col] belongs to
            //   row  = wm*32 + mt*16 + (lane>>2) + 8h
            //   code = nchunk0 + wn*64 + nt*8 + 2*(lane&3) + col
            float keyv[2][8][4];
            #pragma unroll
            for (int mt = 0; mt < 2; ++mt)
                #pragma unroll
                for (int nt = 0; nt < 8; ++nt)
                    #pragma unroll
                    for (int z = 0; z < 4; ++z) {
                        int nloc = wn * 64 + nt * 8 + 2 * (lane & 3) + (z & 1);
                        keyv[mt][nt][z] = fmaf(-2.0f, acc[mt][nt][z], cn_sh[nloc]);
                    }
            #pragma unroll
            for (int mt = 0; mt < 2; ++mt)
                #pragma unroll
                for (int h = 0; h < 2; ++h) {
                    int mloc = wm * 32 + mt * 16 + (lane >> 2) + 8 * h;
                    float mv = __int_as_float(0x7f800000);
                    #pragma unroll
                    for (int nt = 0; nt < 8; ++nt) {
                        float v0 = keyv[mt][nt][2 * h + 0];
                        float v1 = keyv[mt][nt][2 * h + 1];
                        mv = fminf(mv, fminf(v0, v1));
                    }
                    // min over the 4 lanes sharing this row
                    mv = fminf(mv, __shfl_xor_sync(0xffffffffu, mv, 1));
                    mv = fminf(mv, __shfl_xor_sync(0xffffffffu, mv, 2));
                    if ((lane & 3) == 0) atomicMin(&smin[mloc], encf(mv));
                }
            __syncthreads();
            #pragma unroll
            for (int mt = 0; mt < 2; ++mt)
                #pragma unroll
                for (int h = 0; h < 2; ++h) {
                    int mloc = wm * 32 + mt * 16 + (lane >> 2) + 8 * h;
                    float lim = decf(smin[mloc]) + THRESH;
                    #pragma unroll
                    for (int nt = 0; nt < 8; ++nt)
                        #pragma unroll
                        for (int col = 0; col < 2; ++col) {
                            float v = keyv[mt][nt][2 * h + col];
                            if (v <= lim) {
                                int code = nchunk0 + wn * 64 + nt * 8 + 2 * (lane & 3) + col;
                                int p = atomicAdd(&cnt[mloc], 1);
                                if (p < SLOTS) slots[mloc * SLOTS + p] = (short)code;
                            }
                        }
                }
            // loop-top __syncthreads protects slots/smin before next chunk
        }
    }
    __syncthreads();
    if (tid < 128) g_ccnt[m0 + tid] = cnt[tid];
    for (int i = tid; i < 128 * SLOTS; i += 256)
        g_cand[(m0 + i / SLOTS) * SLOTS + (i % SLOTS)] = slots[i];
}

// ---------------------------------------------------------------------------
// K3 (Phase B): exact fp32 rescore of candidates. One warp per row.
// Sequential k-order dot + the reference rounding chain fl(fl(xn-2s)+cn),
// first-index tie-break — bit-identical bmu to the known-good scalar kernel.
// ---------------------------------------------------------------------------
__global__ __launch_bounds__(256) void k_rescore(const float* __restrict__ cb) {
    __shared__ float xsh[8][DDIM];
    int wid  = threadIdx.x >> 5;
    int lane = threadIdx.x & 31;
    int row  = blockIdx.x * 8 + wid;

    for (int j = lane; j < DDIM; j += 32) xsh[wid][j] = g_patch[row * DDIM + j];
    __syncwarp();

    int   c  = g_ccnt[row];
    float xn = g_xnorm[row];
    float bv = __int_as_float(0x7f800000);
    int   bi = 0x7fffffff;

    if (c <= SLOTS) {
        if (lane < c) {
            int code = g_cand[row * SLOTS + lane];
            const float* cr = cb + code * DDIM;
            float s = 0.0f;
            #pragma unroll 8
            for (int j = 0; j < DDIM; ++j) s = fmaf(xsh[wid][j], cr[j], s);
            bv = __fadd_rn(__fmaf_rn(-2.0f, s, xn), g_cnorm[code]);
            bi = code;
        }
    } else {
        for (int code = lane; code < KCODES; code += 32) {
            const float* cr = cb + code * DDIM;
            float s = 0.0f;
            #pragma unroll 8
            for (int j = 0; j < DDIM; ++j) s = fmaf(xsh[wid][j], cr[j], s);
            float v = __fadd_rn(__fmaf_rn(-2.0f, s, xn), g_cnorm[code]);
            if (v < bv || (v == bv && code < bi)) { bv = v; bi = code; }
        }
    }
    #pragma unroll
    for (int o = 16; o; o >>= 1) {
        float ov = __shfl_xor_sync(0xffffffffu, bv, o);
        int   oi = __shfl_xor_sync(0xffffffffu, bi, o);
        if (ov < bv || (ov == bv && oi < bi)) { bv = ov; bi = oi; }
    }
    if (lane == 0) g_bmu[row] = bi;
}

// ---------------------------------------------------------------------------
// K4: gather smoothed[bmu] and un-patchify directly into the output layout
// ---------------------------------------------------------------------------
__global__ void k_output(float* __restrict__ out) {
    int idx = blockIdx.x * blockDim.x + threadIdx.x;
    int w = idx & 63;
    int h = (idx >> 6) & 63;
    int c = (idx >> 12) & 15;
    int n = idx >> 16;
    int i = (n << 8) + ((h >> 2) << 4) + (w >> 2);
    int d = (c << 4) + ((h & 3) << 2) + (w & 3);
    out[idx] = g_smooth[g_bmu[i] * DDIM + d];
}

// ---------------------------------------------------------------------------
extern "C" void kernel_launch(void* const* d_in, const int* in_sizes, int n_in,
                              void* d_out, int out_size) {
    const float* x  = (const float*)d_in[0];   // (128,16,64,64)
    const float* cb = (const float*)d_in[1];   // (1024,256)
    float* out = (float*)d_out;

    k_patchify<<<NPATCH, 64>>>(x);
    k_cnorm  <<<KCODES / 8, 256>>>(cb);
    k_smooth <<<KCODES / 4, 256>>>(cb);
    k_prune  <<<NPATCH / 128, 256>>>();
    k_rescore<<<NPATCH / 8, 256>>>(cb);
    k_output <<<NPATCH * DDIM / 256, 256>>>(out);
}

// round 7
// speedup vs baseline: 3.5592x; 1.5493x over previous
#include <cuda_runtime.h>
#include <cuda_bf16.h>
#include <cstdint>

// Problem constants
#define NPATCH   32768      // 128 batch * 16*16 patches
#define DDIM     256        // 16 channels * 4*4 patch
#define KCODES   1024
// 1/(2*variance) with variance = -(256 / (2*ln 0.1))  =>  inv2var = ln(10)/256
#define INV2VAR  0.0089944730195076785f
#define SLOTS    28
#define THRESH_DOT 2e-3f    // on dot' scale (= 4e-3 on key scale)

// Scratch (static device globals; no runtime allocation)
__device__ float          g_patch [NPATCH * DDIM];   // fp32 patchified x (rescore)
__device__ __nv_bfloat16  g_patch16[NPATCH * DDIM];  // bf16 copy (tensor prune)
__device__ __nv_bfloat16  g_cb16  [KCODES * DDIM];
__device__ float          g_xnorm [NPATCH];
__device__ float          g_cnorm [KCODES];
__device__ float          g_smooth[KCODES * DDIM];
__device__ short          g_cand  [NPATCH * SLOTS];
__device__ int            g_ccnt  [NPATCH];
__device__ int            g_bmu   [NPATCH];

// ---- monotone float<->uint encoding for atomicMax over floats -------------
__device__ __forceinline__ unsigned encf(float f) {
    unsigned u = __float_as_uint(f);
    return (u & 0x80000000u) ? ~u : (u | 0x80000000u);
}
__device__ __forceinline__ float decf(unsigned u) {
    u = (u & 0x80000000u) ? (u & 0x7fffffffu) : ~u;
    return __uint_as_float(u);
}

// ---- tensor-core primitives ----------------------------------------------
__device__ __forceinline__ void ldsm_x4(uint32_t (&r)[4], uint32_t saddr) {
    asm volatile("ldmatrix.sync.aligned.m8n8.x4.shared.b16 {%0,%1,%2,%3}, [%4];"
                 : "=r"(r[0]), "=r"(r[1]), "=r"(r[2]), "=r"(r[3]) : "r"(saddr));
}
__device__ __forceinline__ void mma_bf16(float (&d)[4], const uint32_t (&a)[4],
                                         uint32_t b0, uint32_t b1) {
    asm volatile("mma.sync.aligned.m16n8k16.row.col.f32.bf16.bf16.f32 "
                 "{%0,%1,%2,%3}, {%4,%5,%6,%7}, {%8,%9}, {%0,%1,%2,%3};"
                 : "+f"(d[0]), "+f"(d[1]), "+f"(d[2]), "+f"(d[3])
                 : "r"(a[0]), "r"(a[1]), "r"(a[2]), "r"(a[3]), "r"(b0), "r"(b1));
}

// ---------------------------------------------------------------------------
// K0: patchify + per-patch norm + bf16 copy. 256 threads = 4 patches.
// ---------------------------------------------------------------------------
__global__ void k_patchify(const float* __restrict__ x) {
    __shared__ float red[4][2];
    int t   = threadIdx.x & 63;
    int sub = threadIdx.x >> 6;
    int i = blockIdx.x * 4 + sub;
    int n = i >> 8, rem = i & 255;
    int ph = rem >> 4, pw = rem & 15;
    int c = t >> 2, py = t & 3;
    float4 v = *(const float4*)&x[(((n * 16 + c) * 64 + ph * 4 + py) * 64 + pw * 4)];
    int dst = i * DDIM + c * 16 + py * 4;
    *(float4*)&g_patch[dst] = v;
    __nv_bfloat162 b01 = __floats2bfloat162_rn(v.x, v.y);
    __nv_bfloat162 b23 = __floats2bfloat162_rn(v.z, v.w);
    *(__nv_bfloat162*)&g_patch16[dst]     = b01;
    *(__nv_bfloat162*)&g_patch16[dst + 2] = b23;
    float s = fmaf(v.x, v.x, fmaf(v.y, v.y, fmaf(v.z, v.z, v.w * v.w)));
    #pragma unroll
    for (int o = 16; o; o >>= 1) s += __shfl_xor_sync(0xffffffffu, s, o);
    if ((t & 31) == 0) red[sub][t >> 5] = s;
    __syncthreads();
    if (t == 0) g_xnorm[i] = red[sub][0] + red[sub][1];
}

// ---------------------------------------------------------------------------
// K1a: per-code squared norms + bf16 codebook copy (one warp per row)
// ---------------------------------------------------------------------------
__global__ void k_cnorm(const float* __restrict__ cb) {
    int row  = blockIdx.x * 8 + (threadIdx.x >> 5);
    int lane = threadIdx.x & 31;
    const float* p = cb + row * DDIM;
    float s = 0.0f;
    #pragma unroll
    for (int j = 0; j < DDIM / 32; ++j) {
        float v = p[lane + j * 32];
        g_cb16[row * DDIM + lane + j * 32] = __float2bfloat16(v);
        s = fmaf(v, v, s);
    }
    #pragma unroll
    for (int o = 16; o; o >>= 1) s += __shfl_xor_sync(0xffffffffu, s, o);
    if (lane == 0) g_cnorm[row] = s;
}

// ---------------------------------------------------------------------------
// K1b: Gaussian-smoothed codebook (radius-64 truncation, weights <1e-16 dropped)
// ---------------------------------------------------------------------------
__global__ void k_smooth(const float* __restrict__ cb) {
    __shared__ float wd[136];
    int jbase = blockIdx.x * 4;
    int tid = threadIdx.x;
    if (tid < 136) {
        float dd = (float)(tid - 67);
        wd[tid] = expf(-(dd * dd) * INV2VAR);
    }
    __syncthreads();
    float acc[4] = {0.f, 0.f, 0.f, 0.f};
    int klo = jbase - 64;      if (klo < 0) klo = 0;
    int khi = jbase + 3 + 64;  if (khi > KCODES - 1) khi = KCODES - 1;
    for (int kk = klo; kk <= khi; ++kk) {
        float v = cb[kk * DDIM + tid];
        int base = kk - jbase + 67;
        #pragma unroll
        for (int t = 0; t < 4; ++t)
            acc[t] = fmaf(wd[base - t], v, acc[t]);
    }
    #pragma unroll
    for (int t = 0; t < 4; ++t)
        g_smooth[(jbase + t) * DDIM + tid] = acc[t];
}

// ---------------------------------------------------------------------------
// K2 (Phase A): bf16 tensor-core prune, cnorm folded into accumulator init.
// Block: 128 rows x 1024 codes (8 chunks of 128), 8 warps, warp tile 32x64.
// acc starts at -cnorm/2, MMA adds x.c  =>  acc = dot' = s - cn/2.
// argmin(cn - 2s) == argmax(dot'). Per-row running max in shared; collect
// codes with dot' >= runmax - THRESH_DOT. Winner provably in the set.
// ---------------------------------------------------------------------------
__global__ __launch_bounds__(256, 2) void k_prune() {
    __shared__ __align__(16) __nv_bfloat16 Xs[128 * 40];  // pad 32->40 for LDSM
    __shared__ __align__(16) __nv_bfloat16 Cs[128 * 40];
    __shared__ float    cn_sh[128];
    __shared__ unsigned smax[128];
    __shared__ int      cnt[128];
    __shared__ short    slots[128 * SLOTS];

    int tid  = threadIdx.x;
    int lane = tid & 31;
    int wid  = tid >> 5;
    int wm   = wid & 3;            // m band: 32 rows
    int wn   = wid >> 2;           // n band: 64 codes
    int m0   = blockIdx.x * 128;

    if (tid < 128) { smax[tid] = 0u; cnt[tid] = 0; }

    uint32_t xs_base = (uint32_t)__cvta_generic_to_shared(Xs);
    uint32_t cs_base = (uint32_t)__cvta_generic_to_shared(Cs);

    int r0c = (tid) >> 2,        g0c = (tid) & 3;
    int r1c = (tid + 256) >> 2,  g1c = (tid + 256) & 3;

    uint4 px0, px1, pc0, pc1;
    auto glob_load = [&](int ls) {
        int k0 = (ls & 7) * 32;
        int n0 = (ls >> 3) << 7;
        px0 = *(const uint4*)&g_patch16[(m0 + r0c) * DDIM + k0 + g0c * 8];
        px1 = *(const uint4*)&g_patch16[(m0 + r1c) * DDIM + k0 + g1c * 8];
        pc0 = *(const uint4*)&g_cb16  [(n0 + r0c) * DDIM + k0 + g0c * 8];
        pc1 = *(const uint4*)&g_cb16  [(n0 + r1c) * DDIM + k0 + g1c * 8];
    };

    float acc[2][8][4];
    glob_load(0);

    for (int ls = 0; ls < 64; ++ls) {
        int s = ls & 7;
        int nchunk0 = (ls >> 3) << 7;
        __syncthreads();                       // prev compute / epilogue done
        *(uint4*)&Xs[r0c * 40 + g0c * 8] = px0;
        *(uint4*)&Xs[r1c * 40 + g1c * 8] = px1;
        *(uint4*)&Cs[r0c * 40 + g0c * 8] = pc0;
        *(uint4*)&Cs[r1c * 40 + g1c * 8] = pc1;
        if (s == 0 && tid < 128) cn_sh[tid] = g_cnorm[nchunk0 + tid];
        __syncthreads();
        if (s == 0) {
            // init accumulators to -cn/2 (fold cnorm into the GEMM)
            #pragma unroll
            for (int nt = 0; nt < 8; ++nt)
                #pragma unroll
                for (int z = 0; z < 4; ++z) {
                    int nloc = wn * 64 + nt * 8 + 2 * (lane & 3) + (z & 1);
                    float v = -0.5f * cn_sh[nloc];
                    acc[0][nt][z] = v;
                    acc[1][nt][z] = v;
                }
        }
        if (ls < 63) glob_load(ls + 1);        // prefetch next slab

        #pragma unroll
        for (int kstep = 0; kstep < 2; ++kstep) {
            uint32_t a[2][4];
            #pragma unroll
            for (int mt = 0; mt < 2; ++mt) {
                int row = wm * 32 + mt * 16 + (lane & 15);
                ldsm_x4(a[mt], xs_base + (uint32_t)((row * 40 + kstep * 16 + (lane >> 4) * 8) * 2));
            }
            #pragma unroll
            for (int ntp = 0; ntp < 4; ++ntp) {
                uint32_t b[4];
                int row = wn * 64 + ntp * 16 + (lane & 15);
                ldsm_x4(b, cs_base + (uint32_t)((row * 40 + kstep * 16 + (lane >> 4) * 8) * 2));
                #pragma unroll
                for (int mt = 0; mt < 2; ++mt) {
                    mma_bf16(acc[mt][2 * ntp + 0], a[mt], b[0], b[2]);
                    mma_bf16(acc[mt][2 * ntp + 1], a[mt], b[1], b[3]);
                }
            }
        }

        if (s == 7) {
            // ---- epilogue: running max + loose candidate collection ----
            // acc[mt][nt][2h+col]:
            //   row  = wm*32 + mt*16 + (lane>>2) + 8h
            //   code = nchunk0 + wn*64 + nt*8 + 2*(lane&3) + col
            #pragma unroll
            for (int mt = 0; mt < 2; ++mt)
                #pragma unroll
                for (int h = 0; h < 2; ++h) {
                    int mloc = wm * 32 + mt * 16 + (lane >> 2) + 8 * h;
                    float mv = acc[mt][0][2 * h];
                    #pragma unroll
                    for (int nt = 0; nt < 8; ++nt) {
                        mv = fmaxf(mv, acc[mt][nt][2 * h + 0]);
                        mv = fmaxf(mv, acc[mt][nt][2 * h + 1]);
                    }
                    mv = fmaxf(mv, __shfl_xor_sync(0xffffffffu, mv, 1));
                    mv = fmaxf(mv, __shfl_xor_sync(0xffffffffu, mv, 2));
                    if ((lane & 3) == 0) atomicMax(&smax[mloc], encf(mv));
                }
            __syncthreads();
            #pragma unroll
            for (int mt = 0; mt < 2; ++mt)
                #pragma unroll
                for (int h = 0; h < 2; ++h) {
                    int mloc = wm * 32 + mt * 16 + (lane >> 2) + 8 * h;
                    float lim = decf(smax[mloc]) - THRESH_DOT;
                    #pragma unroll
                    for (int nt = 0; nt < 8; ++nt)
                        #pragma unroll
                        for (int col = 0; col < 2; ++col) {
                            float v = acc[mt][nt][2 * h + col];
                            if (v >= lim) {
                                int code = nchunk0 + wn * 64 + nt * 8 + 2 * (lane & 3) + col;
                                int p = atomicAdd(&cnt[mloc], 1);
                                if (p < SLOTS) slots[mloc * SLOTS + p] = (short)code;
                            }
                        }
                }
            // loop-top __syncthreads protects slots/smax before next chunk
        }
    }
    __syncthreads();
    if (tid < 128) g_ccnt[m0 + tid] = cnt[tid];
    for (int i = tid; i < 128 * SLOTS; i += 256)
        g_cand[(m0 + i / SLOTS) * SLOTS + (i % SLOTS)] = slots[i];
}

// ---------------------------------------------------------------------------
// K3 (Phase B): exact fp32 rescore, coalesced. One warp per row; the 32 lanes
// split the 256 dims (2x float4 each), shfl-reduce per candidate.
// v = fl(fl(xn - 2s) + cn), lowest-code tie-break (deterministic regardless
// of candidate slot order).
// ---------------------------------------------------------------------------
__global__ __launch_bounds__(256) void k_rescore(const float* __restrict__ cb) {
    int wid  = threadIdx.x >> 5;
    int lane = threadIdx.x & 31;
    int row  = blockIdx.x * 8 + wid;

    float4 x0 = *(const float4*)&g_patch[row * DDIM + lane * 8];
    float4 x1 = *(const float4*)&g_patch[row * DDIM + lane * 8 + 4];

    int   c  = g_ccnt[row];
    float xn = g_xnorm[row];
    float bv = __int_as_float(0x7f800000);
    int   bi = 0x7fffffff;

    if (c <= SLOTS) {
        for (int p = 0; p < c; ++p) {
            int code = g_cand[row * SLOTS + p];
            float4 c0 = *(const float4*)&cb[code * DDIM + lane * 8];
            float4 c1 = *(const float4*)&cb[code * DDIM + lane * 8 + 4];
            float s = x0.x * c0.x;
            s = fmaf(x0.y, c0.y, s); s = fmaf(x0.z, c0.z, s); s = fmaf(x0.w, c0.w, s);
            s = fmaf(x1.x, c1.x, s); s = fmaf(x1.y, c1.y, s);
            s = fmaf(x1.z, c1.z, s); s = fmaf(x1.w, c1.w, s);
            #pragma unroll
            for (int o = 16; o; o >>= 1) s += __shfl_xor_sync(0xffffffffu, s, o);
            float v = __fadd_rn(__fmaf_rn(-2.0f, s, xn), g_cnorm[code]);
            if (v < bv || (v == bv && code < bi)) { bv = v; bi = code; }
        }
    } else {
        // overflow fallback: full scan (coalesced per candidate as well)
        for (int code = 0; code < KCODES; ++code) {
            float4 c0 = *(const float4*)&cb[code * DDIM + lane * 8];
            float4 c1 = *(const float4*)&cb[code * DDIM + lane * 8 + 4];
            float s = x0.x * c0.x;
            s = fmaf(x0.y, c0.y, s); s = fmaf(x0.z, c0.z, s); s = fmaf(x0.w, c0.w, s);
            s = fmaf(x1.x, c1.x, s); s = fmaf(x1.y, c1.y, s);
            s = fmaf(x1.z, c1.z, s); s = fmaf(x1.w, c1.w, s);
            #pragma unroll
            for (int o = 16; o; o >>= 1) s += __shfl_xor_sync(0xffffffffu, s, o);
            float v = __fadd_rn(__fmaf_rn(-2.0f, s, xn), g_cnorm[code]);
            if (v < bv || (v == bv && code < bi)) { bv = v; bi = code; }
        }
    }
    if (lane == 0) g_bmu[row] = bi;
}

// ---------------------------------------------------------------------------
// K4: gather smoothed[bmu] -> output, float4 vectorized (d%4==0 aligned)
// ---------------------------------------------------------------------------
__global__ void k_output(float* __restrict__ out) {
    int e = blockIdx.x * blockDim.x + threadIdx.x;   // one float4 per thread
    int idx = e * 4;
    int w = idx & 63;
    int h = (idx >> 6) & 63;
    int c = (idx >> 12) & 15;
    int n = idx >> 16;
    int i = (n << 8) + ((h >> 2) << 4) + (w >> 2);
    int d = (c << 4) + ((h & 3) << 2);               // w&3 spans the float4
    float4 v = *(const float4*)&g_smooth[g_bmu[i] * DDIM + d];
    *(float4*)&out[idx] = v;
}

// ---------------------------------------------------------------------------
extern "C" void kernel_launch(void* const* d_in, const int* in_sizes, int n_in,
                              void* d_out, int out_size) {
    const float* x  = (const float*)d_in[0];   // (128,16,64,64)
    const float* cb = (const float*)d_in[1];   // (1024,256)
    float* out = (float*)d_out;

    k_patchify<<<NPATCH / 4, 256>>>(x);
    k_cnorm  <<<KCODES / 8, 256>>>(cb);
    k_smooth <<<KCODES / 4, 256>>>(cb);
    k_prune  <<<NPATCH / 128, 256>>>();
    k_rescore<<<NPATCH / 8, 256>>>(cb);
    k_output <<<NPATCH * DDIM / 1024, 256>>>(out);
}

// round 8
// speedup vs baseline: 5.5771x; 1.5669x over previous
#include <cuda_runtime.h>
#include <cuda_bf16.h>
#include <cstdint>

// Problem constants
#define NPATCH   32768      // 128 batch * 16*16 patches
#define DDIM     256        // 16 channels * 4*4 patch
#define KCODES   1024
// 1/(2*variance) with variance = -(256 / (2*ln 0.1))  =>  inv2var = ln(10)/256
#define INV2VAR  0.0089944730195076785f
#define SLOTS    28
#define THRESH_DOT 2e-3f    // on dot' scale (= 4e-3 on key scale)

// Scratch (static device globals; no runtime allocation)
__device__ float          g_patch [NPATCH * DDIM];   // fp32 patchified x (rescore)
__device__ __nv_bfloat16  g_patch16[NPATCH * DDIM];  // bf16 copy (tensor prune)
__device__ __nv_bfloat16  g_cb16  [KCODES * DDIM];
__device__ float          g_xnorm [NPATCH];
__device__ float          g_cnorm [KCODES];
__device__ float          g_smooth[KCODES * DDIM];
__device__ short          g_cand  [NPATCH * SLOTS];
__device__ int            g_ccnt  [NPATCH];
__device__ int            g_bmu   [NPATCH];

// ---- monotone float<->uint encoding for atomicMax over floats -------------
__device__ __forceinline__ unsigned encf(float f) {
    unsigned u = __float_as_uint(f);
    return (u & 0x80000000u) ? ~u : (u | 0x80000000u);
}
__device__ __forceinline__ float decf(unsigned u) {
    u = (u & 0x80000000u) ? (u & 0x7fffffffu) : ~u;
    return __uint_as_float(u);
}

// ---- tensor-core primitives ----------------------------------------------
__device__ __forceinline__ void ldsm_x4(uint32_t (&r)[4], uint32_t saddr) {
    asm volatile("ldmatrix.sync.aligned.m8n8.x4.shared.b16 {%0,%1,%2,%3}, [%4];"
                 : "=r"(r[0]), "=r"(r[1]), "=r"(r[2]), "=r"(r[3]) : "r"(saddr));
}
__device__ __forceinline__ void mma_bf16(float (&d)[4], const uint32_t (&a)[4],
                                         uint32_t b0, uint32_t b1) {
    asm volatile("mma.sync.aligned.m16n8k16.row.col.f32.bf16.bf16.f32 "
                 "{%0,%1,%2,%3}, {%4,%5,%6,%7}, {%8,%9}, {%0,%1,%2,%3};"
                 : "+f"(d[0]), "+f"(d[1]), "+f"(d[2]), "+f"(d[3])
                 : "r"(a[0]), "r"(a[1]), "r"(a[2]), "r"(a[3]), "r"(b0), "r"(b1));
}

// XOR swizzle for 64B-row smem tiles: chunk' = chunk ^ ((row>>1)&3).
// Conflict-free for STS.128 (rows 0..7 x chunks) and LDSM (16 rows, 1 chunk).
__device__ __forceinline__ uint32_t sw_off(int row, int chunk) {
    return (uint32_t)(row * 64 + ((chunk ^ ((row >> 1) & 3)) << 4));
}

// ---------------------------------------------------------------------------
// K0: patchify + per-patch norm + bf16 copy. 256 threads = 4 patches.
// ---------------------------------------------------------------------------
__global__ void k_patchify(const float* __restrict__ x) {
    __shared__ float red[4][2];
    int t   = threadIdx.x & 63;
    int sub = threadIdx.x >> 6;
    int i = blockIdx.x * 4 + sub;
    int n = i >> 8, rem = i & 255;
    int ph = rem >> 4, pw = rem & 15;
    int c = t >> 2, py = t & 3;
    float4 v = *(const float4*)&x[(((n * 16 + c) * 64 + ph * 4 + py) * 64 + pw * 4)];
    int dst = i * DDIM + c * 16 + py * 4;
    *(float4*)&g_patch[dst] = v;
    __nv_bfloat162 b01 = __floats2bfloat162_rn(v.x, v.y);
    __nv_bfloat162 b23 = __floats2bfloat162_rn(v.z, v.w);
    *(__nv_bfloat162*)&g_patch16[dst]     = b01;
    *(__nv_bfloat162*)&g_patch16[dst + 2] = b23;
    float s = fmaf(v.x, v.x, fmaf(v.y, v.y, fmaf(v.z, v.z, v.w * v.w)));
    #pragma unroll
    for (int o = 16; o; o >>= 1) s += __shfl_xor_sync(0xffffffffu, s, o);
    if ((t & 31) == 0) red[sub][t >> 5] = s;
    __syncthreads();
    if (t == 0) g_xnorm[i] = red[sub][0] + red[sub][1];
}

// ---------------------------------------------------------------------------
// K1a: per-code squared norms + bf16 codebook copy (one warp per row)
// ---------------------------------------------------------------------------
__global__ void k_cnorm(const float* __restrict__ cb) {
    int row  = blockIdx.x * 8 + (threadIdx.x >> 5);
    int lane = threadIdx.x & 31;
    const float* p = cb + row * DDIM;
    float s = 0.0f;
    #pragma unroll
    for (int j = 0; j < DDIM / 32; ++j) {
        float v = p[lane + j * 32];
        g_cb16[row * DDIM + lane + j * 32] = __float2bfloat16(v);
        s = fmaf(v, v, s);
    }
    #pragma unroll
    for (int o = 16; o; o >>= 1) s += __shfl_xor_sync(0xffffffffu, s, o);
    if (lane == 0) g_cnorm[row] = s;
}

// ---------------------------------------------------------------------------
// K1b: Gaussian-smoothed codebook (radius-64 truncation, weights <1e-16 dropped)
// ---------------------------------------------------------------------------
__global__ void k_smooth(const float* __restrict__ cb) {
    __shared__ float wd[136];
    int jbase = blockIdx.x * 4;
    int tid = threadIdx.x;
    if (tid < 136) {
        float dd = (float)(tid - 67);
        wd[tid] = expf(-(dd * dd) * INV2VAR);
    }
    __syncthreads();
    float acc[4] = {0.f, 0.f, 0.f, 0.f};
    int klo = jbase - 64;      if (klo < 0) klo = 0;
    int khi = jbase + 3 + 64;  if (khi > KCODES - 1) khi = KCODES - 1;
    for (int kk = klo; kk <= khi; ++kk) {
        float v = cb[kk * DDIM + tid];
        int base = kk - jbase + 67;
        #pragma unroll
        for (int t = 0; t < 4; ++t)
            acc[t] = fmaf(wd[base - t], v, acc[t]);
    }
    #pragma unroll
    for (int t = 0; t < 4; ++t)
        g_smooth[(jbase + t) * DDIM + tid] = acc[t];
}

// ---------------------------------------------------------------------------
// K2 (Phase A): bf16 tensor-core prune, single-sync double-buffered pipeline.
// Block: 128 rows x 1024 codes (8 chunks of 128), 8 warps, warp tile 32x64.
// acc starts at -cnorm/2; MMA adds x.c  =>  acc = dot' = s - cn/2.
// argmin(cn - 2s) == argmax(dot'). Per-row running max in shared; collect
// codes with dot' >= runmax - THRESH_DOT. Winner provably in the set.
// Pipeline per 32-dim slab: STS(regs from prior LDG) -> one syncthreads ->
// prefetch LDG(next) -> LDSM+MMA on just-published buffer.
// ---------------------------------------------------------------------------
__global__ __launch_bounds__(256, 2) void k_prune() {
    __shared__ __align__(128) __nv_bfloat16 Xs[2][128 * 32];  // XOR-swizzled 64B rows
    __shared__ __align__(128) __nv_bfloat16 Cs[2][128 * 32];
    __shared__ float    cn_sh[128];
    __shared__ unsigned smax[128];
    __shared__ int      cnt[128];
    __shared__ short    slots[128 * SLOTS];

    int tid  = threadIdx.x;
    int lane = tid & 31;
    int wid  = tid >> 5;
    int wm   = wid & 3;            // m band: 32 rows
    int wn   = wid >> 2;           // n band: 64 codes
    int m0   = blockIdx.x * 128;

    if (tid < 128) { smax[tid] = 0u; cnt[tid] = 0; cn_sh[tid] = g_cnorm[tid]; }

    uint32_t xs_base[2] = { (uint32_t)__cvta_generic_to_shared(Xs[0]),
                            (uint32_t)__cvta_generic_to_shared(Xs[1]) };
    uint32_t cs_base[2] = { (uint32_t)__cvta_generic_to_shared(Cs[0]),
                            (uint32_t)__cvta_generic_to_shared(Cs[1]) };

    // per-thread load/store pattern: 2 x 16B chunks (8 bf16 each)
    int r0 = tid >> 2,         g0 = tid & 3;
    int r1 = (tid + 256) >> 2, g1 = tid & 3;       // rows 64..127, same chunk col
    uint32_t so_x0 = sw_off(r0, g0), so_x1 = sw_off(r1, g1);

    uint4 px0, px1, pc0, pc1;
    auto glob_load = [&](int ls) {
        int k0 = (ls & 7) * 32;
        int n0 = (ls >> 3) << 7;
        px0 = *(const uint4*)&g_patch16[(m0 + r0) * DDIM + k0 + g0 * 8];
        px1 = *(const uint4*)&g_patch16[(m0 + r1) * DDIM + k0 + g1 * 8];
        pc0 = *(const uint4*)&g_cb16  [(n0 + r0) * DDIM + k0 + g0 * 8];
        pc1 = *(const uint4*)&g_cb16  [(n0 + r1) * DDIM + k0 + g1 * 8];
    };
    auto sts = [&](int buf) {
        *(uint4*)((char*)Xs[buf] + so_x0) = px0;
        *(uint4*)((char*)Xs[buf] + so_x1) = px1;
        *(uint4*)((char*)Cs[buf] + so_x0) = pc0;
        *(uint4*)((char*)Cs[buf] + so_x1) = pc1;
    };

    // LDSM invariants
    int arow[2], brow[4];
    #pragma unroll
    for (int mt = 0; mt < 2; ++mt) arow[mt] = wm * 32 + mt * 16 + (lane & 15);
    #pragma unroll
    for (int nt = 0; nt < 4; ++nt) brow[nt] = wn * 64 + nt * 16 + (lane & 15);
    int ch_hi = lane >> 4;    // chunk offset within kstep pair

    float acc[2][8][4];
    glob_load(0);
    sts(0);                   // slab 0 -> buf 0 (published by first sync)
    glob_load(1);

    for (int ls = 0; ls < 64; ++ls) {
        int s   = ls & 7;
        int buf = ls & 1;
        if (ls > 0) sts(buf);          // regs hold slab ls (loaded in iter ls-1)
        __syncthreads();               // publish slab ls; buffer^1 free
        if (s == 0) {
            // init accumulators to -cn/2 (fold cnorm into the GEMM)
            #pragma unroll
            for (int nt = 0; nt < 8; ++nt)
                #pragma unroll
                for (int z = 0; z < 4; ++z) {
                    int nloc = wn * 64 + nt * 8 + 2 * (lane & 3) + (z & 1);
                    float v = -0.5f * cn_sh[nloc];
                    acc[0][nt][z] = v;
                    acc[1][nt][z] = v;
                }
        }
        if (ls < 63) glob_load(ls + 1);    // prefetch next slab into regs

        #pragma unroll
        for (int kstep = 0; kstep < 2; ++kstep) {
            int kc = kstep * 2 + ch_hi;
            uint32_t a[2][4];
            #pragma unroll
            for (int mt = 0; mt < 2; ++mt)
                ldsm_x4(a[mt], xs_base[buf] + sw_off(arow[mt], kc));
            #pragma unroll
            for (int ntp = 0; ntp < 4; ++ntp) {
                uint32_t b[4];
                ldsm_x4(b, cs_base[buf] + sw_off(brow[ntp], kc));
                #pragma unroll
                for (int mt = 0; mt < 2; ++mt) {
                    mma_bf16(acc[mt][2 * ntp + 0], a[mt], b[0], b[2]);
                    mma_bf16(acc[mt][2 * ntp + 1], a[mt], b[1], b[3]);
                }
            }
        }

        if (s == 7) {
            int nchunk0 = (ls >> 3) << 7;
            // ---- epilogue: running max + loose candidate collection ----
            // acc[mt][nt][2h+col]:
            //   row  = wm*32 + mt*16 + (lane>>2) + 8h
            //   code = nchunk0 + wn*64 + nt*8 + 2*(lane&3) + col
            #pragma unroll
            for (int mt = 0; mt < 2; ++mt)
                #pragma unroll
                for (int h = 0; h < 2; ++h) {
                    int mloc = wm * 32 + mt * 16 + (lane >> 2) + 8 * h;
                    float mv = acc[mt][0][2 * h];
                    #pragma unroll
                    for (int nt = 0; nt < 8; ++nt) {
                        mv = fmaxf(mv, acc[mt][nt][2 * h + 0]);
                        mv = fmaxf(mv, acc[mt][nt][2 * h + 1]);
                    }
                    mv = fmaxf(mv, __shfl_xor_sync(0xffffffffu, mv, 1));
                    mv = fmaxf(mv, __shfl_xor_sync(0xffffffffu, mv, 2));
                    if ((lane & 3) == 0) atomicMax(&smax[mloc], encf(mv));
                }
            __syncthreads();
            #pragma unroll
            for (int mt = 0; mt < 2; ++mt)
                #pragma unroll
                for (int h = 0; h < 2; ++h) {
                    int mloc = wm * 32 + mt * 16 + (lane >> 2) + 8 * h;
                    float lim = decf(smax[mloc]) - THRESH_DOT;
                    #pragma unroll
                    for (int nt = 0; nt < 8; ++nt)
                        #pragma unroll
                        for (int col = 0; col < 2; ++col) {
                            float v = acc[mt][nt][2 * h + col];
                            if (v >= lim) {
                                int code = nchunk0 + wn * 64 + nt * 8 + 2 * (lane & 3) + col;
                                int p = atomicAdd(&cnt[mloc], 1);
                                if (p < SLOTS) slots[mloc * SLOTS + p] = (short)code;
                            }
                        }
                }
            // prefetch next chunk's cnorm (ordered by next top-of-loop sync)
            if (ls < 63 && tid < 128) cn_sh[tid] = g_cnorm[nchunk0 + 128 + tid];
        }
    }
    __syncthreads();
    if (tid < 128) g_ccnt[m0 + tid] = cnt[tid];
    for (int i = tid; i < 128 * SLOTS; i += 256)
        g_cand[(m0 + i / SLOTS) * SLOTS + (i % SLOTS)] = slots[i];
}

// ---------------------------------------------------------------------------
// K3 (Phase B): exact fp32 rescore, coalesced. One warp per row; 32 lanes
// split the 256 dims, shfl-reduce per candidate. v = fl(fl(xn-2s)+cn),
// lowest-code tie-break (deterministic regardless of slot order).
// ---------------------------------------------------------------------------
__global__ __launch_bounds__(256) void k_rescore(const float* __restrict__ cb) {
    int wid  = threadIdx.x >> 5;
    int lane = threadIdx.x & 31;
    int row  = blockIdx.x * 8 + wid;

    float4 x0 = *(const float4*)&g_patch[row * DDIM + lane * 8];
    float4 x1 = *(const float4*)&g_patch[row * DDIM + lane * 8 + 4];

    int   c  = g_ccnt[row];
    float xn = g_xnorm[row];
    float bv = __int_as_float(0x7f800000);
    int   bi = 0x7fffffff;

    int lim = (c <= SLOTS) ? c : KCODES;
    for (int p = 0; p < lim; ++p) {
        int code = (c <= SLOTS) ? g_cand[row * SLOTS + p] : p;
        float4 c0 = *(const float4*)&cb[code * DDIM + lane * 8];
        float4 c1 = *(const float4*)&cb[code * DDIM + lane * 8 + 4];
        float s = x0.x * c0.x;
        s = fmaf(x0.y, c0.y, s); s = fmaf(x0.z, c0.z, s); s = fmaf(x0.w, c0.w, s);
        s = fmaf(x1.x, c1.x, s); s = fmaf(x1.y, c1.y, s);
        s = fmaf(x1.z, c1.z, s); s = fmaf(x1.w, c1.w, s);
        #pragma unroll
        for (int o = 16; o; o >>= 1) s += __shfl_xor_sync(0xffffffffu, s, o);
        float v = __fadd_rn(__fmaf_rn(-2.0f, s, xn), g_cnorm[code]);
        if (v < bv || (v == bv && code < bi)) { bv = v; bi = code; }
    }
    if (lane == 0) g_bmu[row] = bi;
}

// ---------------------------------------------------------------------------
// K4: gather smoothed[bmu] -> output, float4 vectorized (d%4==0 aligned)
// ---------------------------------------------------------------------------
__global__ void k_output(float* __restrict__ out) {
    int e = blockIdx.x * blockDim.x + threadIdx.x;   // one float4 per thread
    int idx = e * 4;
    int w = idx & 63;
    int h = (idx >> 6) & 63;
    int c = (idx >> 12) & 15;
    int n = idx >> 16;
    int i = (n << 8) + ((h >> 2) << 4) + (w >> 2);
    int d = (c << 4) + ((h & 3) << 2);               // w&3 spans the float4
    float4 v = *(const float4*)&g_smooth[g_bmu[i] * DDIM + d];
    *(float4*)&out[idx] = v;
}

// ---------------------------------------------------------------------------
extern "C" void kernel_launch(void* const* d_in, const int* in_sizes, int n_in,
                              void* d_out, int out_size) {
    const float* x  = (const float*)d_in[0];   // (128,16,64,64)
    const float* cb = (const float*)d_in[1];   // (1024,256)
    float* out = (float*)d_out;

    k_patchify<<<NPATCH / 4, 256>>>(x);
    k_cnorm  <<<KCODES / 8, 256>>>(cb);
    k_smooth <<<KCODES / 4, 256>>>(cb);
    k_prune  <<<NPATCH / 128, 256>>>();
    k_rescore<<<NPATCH / 8, 256>>>(cb);
    k_output <<<NPATCH * DDIM / 1024, 256>>>(out);
}

// round 9
// speedup vs baseline: 5.9573x; 1.0682x over previous
#include <cuda_runtime.h>
#include <cuda_bf16.h>
#include <cstdint>

// Problem constants
#define NPATCH   32768      // 128 batch * 16*16 patches
#define DDIM     256        // 16 channels * 4*4 patch
#define KCODES   1024
// 1/(2*variance) with variance = -(256 / (2*ln 0.1))  =>  inv2var = ln(10)/256
#define INV2VAR  0.0089944730195076785f
#define SLOTS    28
#define THRESH_DOT 2e-3f    // on dot' scale (= 4e-3 on key scale)

// Scratch (static device globals; no runtime allocation)
__device__ float          g_patch [NPATCH * DDIM];   // fp32 patchified x (rescore)
__device__ __nv_bfloat16  g_patch16[NPATCH * DDIM];  // bf16 copy (tensor prune)
__device__ __nv_bfloat16  g_cb16  [KCODES * DDIM];
__device__ float          g_xnorm [NPATCH];
__device__ float          g_cnorm [KCODES];
__device__ float          g_smooth[KCODES * DDIM];
__device__ short          g_cand  [NPATCH * SLOTS];
__device__ int            g_ccnt  [NPATCH];
__device__ int            g_bmu   [NPATCH];

// ---- monotone float<->uint encoding for atomicMax over floats -------------
__device__ __forceinline__ unsigned encf(float f) {
    unsigned u = __float_as_uint(f);
    return (u & 0x80000000u) ? ~u : (u | 0x80000000u);
}
__device__ __forceinline__ float decf(unsigned u) {
    u = (u & 0x80000000u) ? (u & 0x7fffffffu) : ~u;
    return __uint_as_float(u);
}

// ---- tensor-core primitives ----------------------------------------------
__device__ __forceinline__ void ldsm_x4(uint32_t (&r)[4], uint32_t saddr) {
    asm volatile("ldmatrix.sync.aligned.m8n8.x4.shared.b16 {%0,%1,%2,%3}, [%4];"
                 : "=r"(r[0]), "=r"(r[1]), "=r"(r[2]), "=r"(r[3]) : "r"(saddr));
}
__device__ __forceinline__ void mma_bf16(float (&d)[4], const uint32_t (&a)[4],
                                         uint32_t b0, uint32_t b1) {
    asm volatile("mma.sync.aligned.m16n8k16.row.col.f32.bf16.bf16.f32 "
                 "{%0,%1,%2,%3}, {%4,%5,%6,%7}, {%8,%9}, {%0,%1,%2,%3};"
                 : "+f"(d[0]), "+f"(d[1]), "+f"(d[2]), "+f"(d[3])
                 : "r"(a[0]), "r"(a[1]), "r"(a[2]), "r"(a[3]), "r"(b0), "r"(b1));
}

// XOR swizzle for 64B-row smem tiles: chunk' = chunk ^ ((row>>1)&3).
// Conflict-free for STS.128 and LDSM.
__device__ __forceinline__ uint32_t sw_off(int row, int chunk) {
    return (uint32_t)(row * 64 + ((chunk ^ ((row >> 1) & 3)) << 4));
}

// dynamic-smem layout for k_prune (bytes)
#define SM_XS     0          // [8][128*32] bf16  = 65536
#define SM_CS     65536      // [2][128*32] bf16  = 16384
#define SM_CN     81920      // float[128]
#define SM_MAX    82432      // unsigned[128]
#define SM_CNT    82944      // int[128]
#define SM_SLOT   83456      // short[128*SLOTS] = 7168
#define SM_TOTAL  90624

// ---------------------------------------------------------------------------
// K0: patchify + per-patch norm + bf16 copy. 256 threads = 4 patches.
// ---------------------------------------------------------------------------
__global__ void k_patchify(const float* __restrict__ x) {
    __shared__ float red[4][2];
    int t   = threadIdx.x & 63;
    int sub = threadIdx.x >> 6;
    int i = blockIdx.x * 4 + sub;
    int n = i >> 8, rem = i & 255;
    int ph = rem >> 4, pw = rem & 15;
    int c = t >> 2, py = t & 3;
    float4 v = *(const float4*)&x[(((n * 16 + c) * 64 + ph * 4 + py) * 64 + pw * 4)];
    int dst = i * DDIM + c * 16 + py * 4;
    *(float4*)&g_patch[dst] = v;
    __nv_bfloat162 b01 = __floats2bfloat162_rn(v.x, v.y);
    __nv_bfloat162 b23 = __floats2bfloat162_rn(v.z, v.w);
    *(__nv_bfloat162*)&g_patch16[dst]     = b01;
    *(__nv_bfloat162*)&g_patch16[dst + 2] = b23;
    float s = fmaf(v.x, v.x, fmaf(v.y, v.y, fmaf(v.z, v.z, v.w * v.w)));
    #pragma unroll
    for (int o = 16; o; o >>= 1) s += __shfl_xor_sync(0xffffffffu, s, o);
    if ((t & 31) == 0) red[sub][t >> 5] = s;
    __syncthreads();
    if (t == 0) g_xnorm[i] = red[sub][0] + red[sub][1];
}

// ---------------------------------------------------------------------------
// K1: codebook prep, merged. Blocks 0..127: cnorm + bf16 copy (one warp/row).
// Blocks 128..383: Gaussian smoothing (4 rows/block, radius-64 truncation).
// ---------------------------------------------------------------------------
__global__ void k_cbprep(const float* __restrict__ cb) {
    __shared__ float wd[136];
    int tid = threadIdx.x;
    if (blockIdx.x < 128) {
        int row  = blockIdx.x * 8 + (tid >> 5);
        int lane = tid & 31;
        const float* p = cb + row * DDIM;
        float s = 0.0f;
        #pragma unroll
        for (int j = 0; j < DDIM / 32; ++j) {
            float v = p[lane + j * 32];
            g_cb16[row * DDIM + lane + j * 32] = __float2bfloat16(v);
            s = fmaf(v, v, s);
        }
        #pragma unroll
        for (int o = 16; o; o >>= 1) s += __shfl_xor_sync(0xffffffffu, s, o);
        if (lane == 0) g_cnorm[row] = s;
    } else {
        int jbase = (blockIdx.x - 128) * 4;
        if (tid < 136) {
            float dd = (float)(tid - 67);
            wd[tid] = expf(-(dd * dd) * INV2VAR);
        }
        __syncthreads();
        float acc[4] = {0.f, 0.f, 0.f, 0.f};
        int klo = jbase - 64;      if (klo < 0) klo = 0;
        int khi = jbase + 3 + 64;  if (khi > KCODES - 1) khi = KCODES - 1;
        for (int kk = klo; kk <= khi; ++kk) {
            float v = cb[kk * DDIM + tid];
            int base = kk - jbase + 67;
            #pragma unroll
            for (int t = 0; t < 4; ++t)
                acc[t] = fmaf(wd[base - t], v, acc[t]);
        }
        #pragma unroll
        for (int t = 0; t < 4; ++t)
            g_smooth[(jbase + t) * DDIM + tid] = acc[t];
    }
}

// ---------------------------------------------------------------------------
// K2 (Phase A): bf16 tensor-core prune, X-resident in smem.
// Block: 128 rows x 1024 codes (8 chunks of 128), 8 warps, warp tile 32x64.
// X tile (128x256 bf16, 64KB) loaded ONCE into Xs[8 slabs][128x32];
// C slabs stream through a 16KB double buffer, one syncthreads per slab.
// acc starts at -cnorm/2; MMA adds x.c => acc = dot' = s - cn/2.
// argmin(cn-2s) == argmax(dot'). Collect codes with dot' >= runmax - THRESH.
// ---------------------------------------------------------------------------
__global__ __launch_bounds__(256, 2) void k_prune() {
    extern __shared__ char smem_raw[];
    __nv_bfloat16* Xs   = (__nv_bfloat16*)(smem_raw + SM_XS);
    __nv_bfloat16* Cs   = (__nv_bfloat16*)(smem_raw + SM_CS);
    float*    cn_sh = (float*)   (smem_raw + SM_CN);
    unsigned* smax  = (unsigned*)(smem_raw + SM_MAX);
    int*      cnt   = (int*)     (smem_raw + SM_CNT);
    short*    slots = (short*)   (smem_raw + SM_SLOT);

    int tid  = threadIdx.x;
    int lane = tid & 31;
    int wid  = tid >> 5;
    int wm   = wid & 3;            // m band: 32 rows
    int wn   = wid >> 2;           // n band: 64 codes
    int m0   = blockIdx.x * 128;

    if (tid < 128) { smax[tid] = 0u; cnt[tid] = 0; cn_sh[tid] = g_cnorm[tid]; }

    uint32_t xs_base = (uint32_t)__cvta_generic_to_shared(Xs);
    uint32_t cs_base = (uint32_t)__cvta_generic_to_shared(Cs);

    // ---- load resident X tile: 4096 16B-chunks, coalesced ----
    #pragma unroll
    for (int i = 0; i < 16; ++i) {
        int cid  = i * 256 + tid;          // 0..4095
        int row  = cid >> 5;               // 32 chunks per 256-dim row
        int c32  = cid & 31;
        int slab = c32 >> 2, chunk = c32 & 3;
        uint4 v = *(const uint4*)&g_patch16[(m0 + row) * DDIM + slab * 32 + chunk * 8];
        *(uint4*)((char*)Xs + slab * 8192 + sw_off(row, chunk)) = v;
    }

    // ---- C streaming state: 2 chunks (16B) per thread per slab ----
    int r0 = tid >> 2,  g0 = tid & 3;
    int r1 = r0 + 64;
    uint32_t so0 = sw_off(r0, g0), so1 = sw_off(r1, g0);

    uint4 pc0, pc1;
    auto glob_loadC = [&](int ls) {
        int k0 = (ls & 7) * 32;
        int n0 = (ls >> 3) << 7;
        pc0 = *(const uint4*)&g_cb16[(n0 + r0) * DDIM + k0 + g0 * 8];
        pc1 = *(const uint4*)&g_cb16[(n0 + r1) * DDIM + k0 + g0 * 8];
    };
    auto stsC = [&](int buf) {
        *(uint4*)((char*)Cs + buf * 8192 + so0) = pc0;
        *(uint4*)((char*)Cs + buf * 8192 + so1) = pc1;
    };

    // LDSM invariants
    int arow[2], brow[4];
    #pragma unroll
    for (int mt = 0; mt < 2; ++mt) arow[mt] = wm * 32 + mt * 16 + (lane & 15);
    #pragma unroll
    for (int nt = 0; nt < 4; ++nt) brow[nt] = wn * 64 + nt * 16 + (lane & 15);
    int ch_hi = lane >> 4;

    float acc[2][8][4];
    glob_loadC(0);
    stsC(0);                  // slab 0 -> buf 0 (published by first sync)
    glob_loadC(1);

    for (int ls = 0; ls < 64; ++ls) {
        int s   = ls & 7;
        int buf = ls & 1;
        if (ls > 0) stsC(buf);         // regs hold slab ls (loaded at iter ls-1)
        __syncthreads();               // publish slab ls (and X on ls==0)
        if (s == 0) {
            // init accumulators to -cn/2 (fold cnorm into the GEMM)
            #pragma unroll
            for (int nt = 0; nt < 8; ++nt)
                #pragma unroll
                for (int z = 0; z < 4; ++z) {
                    int nloc = wn * 64 + nt * 8 + 2 * (lane & 3) + (z & 1);
                    float v = -0.5f * cn_sh[nloc];
                    acc[0][nt][z] = v;
                    acc[1][nt][z] = v;
                }
        }
        if (ls < 63) glob_loadC(ls + 1);   // prefetch next slab into regs

        uint32_t xslab = xs_base + (uint32_t)(s * 8192);
        #pragma unroll
        for (int kstep = 0; kstep < 2; ++kstep) {
            int kc = kstep * 2 + ch_hi;
            uint32_t a[2][4];
            #pragma unroll
            for (int mt = 0; mt < 2; ++mt)
                ldsm_x4(a[mt], xslab + sw_off(arow[mt], kc));
            #pragma unroll
            for (int ntp = 0; ntp < 4; ++ntp) {
                uint32_t b[4];
                ldsm_x4(b, cs_base + (uint32_t)(buf * 8192) + sw_off(brow[ntp], kc));
                #pragma unroll
                for (int mt = 0; mt < 2; ++mt) {
                    mma_bf16(acc[mt][2 * ntp + 0], a[mt], b[0], b[2]);
                    mma_bf16(acc[mt][2 * ntp + 1], a[mt], b[1], b[3]);
                }
            }
        }

        if (s == 7) {
            int nchunk0 = (ls >> 3) << 7;
            // ---- epilogue: running max + loose candidate collection ----
            // acc[mt][nt][2h+col]:
            //   row  = wm*32 + mt*16 + (lane>>2) + 8h
            //   code = nchunk0 + wn*64 + nt*8 + 2*(lane&3) + col
            #pragma unroll
            for (int mt = 0; mt < 2; ++mt)
                #pragma unroll
                for (int h = 0; h < 2; ++h) {
                    int mloc = wm * 32 + mt * 16 + (lane >> 2) + 8 * h;
                    float mv = acc[mt][0][2 * h];
                    #pragma unroll
                    for (int nt = 0; nt < 8; ++nt) {
                        mv = fmaxf(mv, acc[mt][nt][2 * h + 0]);
                        mv = fmaxf(mv, acc[mt][nt][2 * h + 1]);
                    }
                    mv = fmaxf(mv, __shfl_xor_sync(0xffffffffu, mv, 1));
                    mv = fmaxf(mv, __shfl_xor_sync(0xffffffffu, mv, 2));
                    if ((lane & 3) == 0) atomicMax(&smax[mloc], encf(mv));
                }
            __syncthreads();
            #pragma unroll
            for (int mt = 0; mt < 2; ++mt)
                #pragma unroll
                for (int h = 0; h < 2; ++h) {
                    int mloc = wm * 32 + mt * 16 + (lane >> 2) + 8 * h;
                    float lim = decf(smax[mloc]) - THRESH_DOT;
                    #pragma unroll
                    for (int nt = 0; nt < 8; ++nt)
                        #pragma unroll
                        for (int col = 0; col < 2; ++col) {
                            float v = acc[mt][nt][2 * h + col];
                            if (v >= lim) {
                                int code = nchunk0 + wn * 64 + nt * 8 + 2 * (lane & 3) + col;
                                int p = atomicAdd(&cnt[mloc], 1);
                                if (p < SLOTS) slots[mloc * SLOTS + p] = (short)code;
                            }
                        }
                }
            // prefetch next chunk's cnorm (ordered by next top-of-loop sync)
            if (ls < 63 && tid < 128) cn_sh[tid] = g_cnorm[nchunk0 + 128 + tid];
        }
    }
    __syncthreads();
    if (tid < 128) g_ccnt[m0 + tid] = cnt[tid];
    for (int i = tid; i < 128 * SLOTS; i += 256)
        g_cand[(m0 + i / SLOTS) * SLOTS + (i % SLOTS)] = slots[i];
}

// ---------------------------------------------------------------------------
// K3 (Phase B): exact fp32 rescore, coalesced + 4-way candidate batching
// (4 independent shfl-reduce chains interleaved to hide SHFL latency).
// v = fl(fl(xn - 2s) + cn), lowest-code tie-break (order-independent).
// ---------------------------------------------------------------------------
__global__ __launch_bounds__(256) void k_rescore(const float* __restrict__ cb) {
    int wid  = threadIdx.x >> 5;
    int lane = threadIdx.x & 31;
    int row  = blockIdx.x * 8 + wid;

    float4 x0 = *(const float4*)&g_patch[row * DDIM + lane * 8];
    float4 x1 = *(const float4*)&g_patch[row * DDIM + lane * 8 + 4];

    int   c  = g_ccnt[row];
    float xn = g_xnorm[row];
    float bv = __int_as_float(0x7f800000);
    int   bi = 0x7fffffff;

    bool ovf = (c > SLOTS);
    int  lim = ovf ? KCODES : c;

    for (int p = 0; p < lim; p += 4) {
        int codes[4];
        float s[4];
        #pragma unroll
        for (int j = 0; j < 4; ++j) {
            int pp = (p + j < lim) ? (p + j) : (lim - 1);
            codes[j] = ovf ? pp : (int)g_cand[row * SLOTS + pp];
        }
        #pragma unroll
        for (int j = 0; j < 4; ++j) {
            float4 c0 = *(const float4*)&cb[codes[j] * DDIM + lane * 8];
            float4 c1 = *(const float4*)&cb[codes[j] * DDIM + lane * 8 + 4];
            float t = x0.x * c0.x;
            t = fmaf(x0.y, c0.y, t); t = fmaf(x0.z, c0.z, t); t = fmaf(x0.w, c0.w, t);
            t = fmaf(x1.x, c1.x, t); t = fmaf(x1.y, c1.y, t);
            t = fmaf(x1.z, c1.z, t); t = fmaf(x1.w, c1.w, t);
            s[j] = t;
        }
        #pragma unroll
        for (int o = 16; o; o >>= 1)
            #pragma unroll
            for (int j = 0; j < 4; ++j)
                s[j] += __shfl_xor_sync(0xffffffffu, s[j], o);
        #pragma unroll
        for (int j = 0; j < 4; ++j) {
            if (p + j < lim) {
                float v = __fadd_rn(__fmaf_rn(-2.0f, s[j], xn), g_cnorm[codes[j]]);
                if (v < bv || (v == bv && codes[j] < bi)) { bv = v; bi = codes[j]; }
            }
        }
    }
    if (lane == 0) g_bmu[row] = bi;
}

// ---------------------------------------------------------------------------
// K4: gather smoothed[bmu] -> output, float4 vectorized (d%4==0 aligned)
// ---------------------------------------------------------------------------
__global__ void k_output(float* __restrict__ out) {
    int e = blockIdx.x * blockDim.x + threadIdx.x;   // one float4 per thread
    int idx = e * 4;
    int w = idx & 63;
    int h = (idx >> 6) & 63;
    int c = (idx >> 12) & 15;
    int n = idx >> 16;
    int i = (n << 8) + ((h >> 2) << 4) + (w >> 2);
    int d = (c << 4) + ((h & 3) << 2);               // w&3 spans the float4
    float4 v = *(const float4*)&g_smooth[g_bmu[i] * DDIM + d];
    *(float4*)&out[idx] = v;
}

// ---------------------------------------------------------------------------
extern "C" void kernel_launch(void* const* d_in, const int* in_sizes, int n_in,
                              void* d_out, int out_size) {
    const float* x  = (const float*)d_in[0];   // (128,16,64,64)
    const float* cb = (const float*)d_in[1];   // (1024,256)
    float* out = (float*)d_out;

    cudaFuncSetAttribute(k_prune, cudaFuncAttributeMaxDynamicSharedMemorySize,
                         SM_TOTAL);

    k_patchify<<<NPATCH / 4, 256>>>(x);
    k_cbprep <<<128 + KCODES / 4, 256>>>(cb);
    k_prune  <<<NPATCH / 128, 256, SM_TOTAL>>>();
    k_rescore<<<NPATCH / 8, 256>>>(cb);
    k_output <<<NPATCH * DDIM / 1024, 256>>>(out);
}

// round 10
// speedup vs baseline: 6.1623x; 1.0344x over previous
#include <cuda_runtime.h>
#include <cuda_bf16.h>
#include <cstdint>

// Problem constants
#define NPATCH   32768      // 128 batch * 16*16 patches
#define DDIM     256        // 16 channels * 4*4 patch
#define KCODES   1024
// 1/(2*variance) with variance = -(256 / (2*ln 0.1))  =>  inv2var = ln(10)/256
#define INV2VAR  0.0089944730195076785f
#define SLOTS    28
#define THRESH_DOT 8e-4f    // ~30 sigma of bf16 dot-error; candidate margin

// Scratch (static device globals; no runtime allocation)
__device__ __nv_bfloat16  g_patch16[NPATCH * DDIM];  // bf16 patches (tensor prune)
__device__ __nv_bfloat16  g_cb16  [KCODES * DDIM];
__device__ float          g_xnorm [NPATCH];
__device__ float          g_cnorm [KCODES];
__device__ float          g_smooth[KCODES * DDIM];
__device__ short          g_cand  [NPATCH * SLOTS];
__device__ int            g_ccnt  [NPATCH];
__device__ int            g_bmu   [NPATCH];

// ---- monotone float<->uint encoding for atomicMax over floats -------------
__device__ __forceinline__ unsigned encf(float f) {
    unsigned u = __float_as_uint(f);
    return (u & 0x80000000u) ? ~u : (u | 0x80000000u);
}
__device__ __forceinline__ float decf(unsigned u) {
    u = (u & 0x80000000u) ? (u & 0x7fffffffu) : ~u;
    return __uint_as_float(u);
}

// ---- tensor-core primitives ----------------------------------------------
__device__ __forceinline__ void ldsm_x4(uint32_t (&r)[4], uint32_t saddr) {
    asm volatile("ldmatrix.sync.aligned.m8n8.x4.shared.b16 {%0,%1,%2,%3}, [%4];"
                 : "=r"(r[0]), "=r"(r[1]), "=r"(r[2]), "=r"(r[3]) : "r"(saddr));
}
__device__ __forceinline__ void mma_bf16(float (&d)[4], const uint32_t (&a)[4],
                                         uint32_t b0, uint32_t b1) {
    asm volatile("mma.sync.aligned.m16n8k16.row.col.f32.bf16.bf16.f32 "
                 "{%0,%1,%2,%3}, {%4,%5,%6,%7}, {%8,%9}, {%0,%1,%2,%3};"
                 : "+f"(d[0]), "+f"(d[1]), "+f"(d[2]), "+f"(d[3])
                 : "r"(a[0]), "r"(a[1]), "r"(a[2]), "r"(a[3]), "r"(b0), "r"(b1));
}

// XOR swizzle for 64B-row smem tiles: chunk' = chunk ^ ((row>>1)&3).
// Conflict-free for STS.128 and LDSM.
__device__ __forceinline__ uint32_t sw_off(int row, int chunk) {
    return (uint32_t)(row * 64 + ((chunk ^ ((row >> 1) & 3)) << 4));
}

// dynamic-smem layout for k_prune (bytes)
#define SM_XS     0          // [8][128*32] bf16  = 65536
#define SM_CS     65536      // [2][128*32] bf16  = 16384
#define SM_CN     81920      // float[128]
#define SM_MAX    82432      // unsigned[128]
#define SM_CNT    82944      // int[128]
#define SM_SLOT   83456      // short[128*SLOTS] = 7168
#define SM_TOTAL  90624

// ---------------------------------------------------------------------------
// K0: patchify -> bf16 + per-patch norm. 256 threads = 4 patches.
// (fp32 patch buffer eliminated; rescore reads x directly)
// ---------------------------------------------------------------------------
__global__ void k_patchify(const float* __restrict__ x) {
    __shared__ float red[4][2];
    int t   = threadIdx.x & 63;
    int sub = threadIdx.x >> 6;
    int i = blockIdx.x * 4 + sub;
    int n = i >> 8, rem = i & 255;
    int ph = rem >> 4, pw = rem & 15;
    int c = t >> 2, py = t & 3;
    float4 v = *(const float4*)&x[(((n * 16 + c) * 64 + ph * 4 + py) * 64 + pw * 4)];
    int dst = i * DDIM + c * 16 + py * 4;
    __nv_bfloat162 b01 = __floats2bfloat162_rn(v.x, v.y);
    __nv_bfloat162 b23 = __floats2bfloat162_rn(v.z, v.w);
    *(__nv_bfloat162*)&g_patch16[dst]     = b01;
    *(__nv_bfloat162*)&g_patch16[dst + 2] = b23;
    float s = fmaf(v.x, v.x, fmaf(v.y, v.y, fmaf(v.z, v.z, v.w * v.w)));
    #pragma unroll
    for (int o = 16; o; o >>= 1) s += __shfl_xor_sync(0xffffffffu, s, o);
    if ((t & 31) == 0) red[sub][t >> 5] = s;
    __syncthreads();
    if (t == 0) g_xnorm[i] = red[sub][0] + red[sub][1];
}

// ---------------------------------------------------------------------------
// K1: codebook prep, merged. Blocks 0..127: cnorm + bf16 copy (one warp/row).
// Blocks 128..383: Gaussian smoothing (4 rows/block, radius-64 truncation).
// ---------------------------------------------------------------------------
__global__ void k_cbprep(const float* __restrict__ cb) {
    __shared__ float wd[136];
    int tid = threadIdx.x;
    if (blockIdx.x < 128) {
        int row  = blockIdx.x * 8 + (tid >> 5);
        int lane = tid & 31;
        const float* p = cb + row * DDIM;
        float s = 0.0f;
        #pragma unroll
        for (int j = 0; j < DDIM / 32; ++j) {
            float v = p[lane + j * 32];
            g_cb16[row * DDIM + lane + j * 32] = __float2bfloat16(v);
            s = fmaf(v, v, s);
        }
        #pragma unroll
        for (int o = 16; o; o >>= 1) s += __shfl_xor_sync(0xffffffffu, s, o);
        if (lane == 0) g_cnorm[row] = s;
    } else {
        int jbase = (blockIdx.x - 128) * 4;
        if (tid < 136) {
            float dd = (float)(tid - 67);
            wd[tid] = expf(-(dd * dd) * INV2VAR);
        }
        __syncthreads();
        float acc[4] = {0.f, 0.f, 0.f, 0.f};
        int klo = jbase - 64;      if (klo < 0) klo = 0;
        int khi = jbase + 3 + 64;  if (khi > KCODES - 1) khi = KCODES - 1;
        for (int kk = klo; kk <= khi; ++kk) {
            float v = cb[kk * DDIM + tid];
            int base = kk - jbase + 67;
            #pragma unroll
            for (int t = 0; t < 4; ++t)
                acc[t] = fmaf(wd[base - t], v, acc[t]);
        }
        #pragma unroll
        for (int t = 0; t < 4; ++t)
            g_smooth[(jbase + t) * DDIM + tid] = acc[t];
    }
}

// ---------------------------------------------------------------------------
// K2 (Phase A): bf16 tensor-core prune, X-resident in smem.
// Block: 128 rows x 1024 codes (8 chunks of 128), 8 warps, warp tile 32x64.
// X tile (128x256 bf16, 64KB) loaded ONCE into Xs[8 slabs][128x32];
// C slabs stream through a 16KB double buffer, one syncthreads per slab.
// acc starts at -cnorm/2; MMA adds x.c => acc = dot' = s - cn/2.
// argmin(cn-2s) == argmax(dot'). Collect codes with dot' >= runmax - THRESH.
// ---------------------------------------------------------------------------
__global__ __launch_bounds__(256, 2) void k_prune() {
    extern __shared__ char smem_raw[];
    __nv_bfloat16* Xs   = (__nv_bfloat16*)(smem_raw + SM_XS);
    __nv_bfloat16* Cs   = (__nv_bfloat16*)(smem_raw + SM_CS);
    float*    cn_sh = (float*)   (smem_raw + SM_CN);
    unsigned* smax  = (unsigned*)(smem_raw + SM_MAX);
    int*      cnt   = (int*)     (smem_raw + SM_CNT);
    short*    slots = (short*)   (smem_raw + SM_SLOT);

    int tid  = threadIdx.x;
    int lane = tid & 31;
    int wid  = tid >> 5;
    int wm   = wid & 3;            // m band: 32 rows
    int wn   = wid >> 2;           // n band: 64 codes
    int m0   = blockIdx.x * 128;

    if (tid < 128) { smax[tid] = 0u; cnt[tid] = 0; cn_sh[tid] = g_cnorm[tid]; }

    uint32_t xs_base = (uint32_t)__cvta_generic_to_shared(Xs);
    uint32_t cs_base = (uint32_t)__cvta_generic_to_shared(Cs);

    // ---- load resident X tile: 4096 16B-chunks, coalesced ----
    #pragma unroll
    for (int i = 0; i < 16; ++i) {
        int cid  = i * 256 + tid;          // 0..4095
        int row  = cid >> 5;               // 32 chunks per 256-dim row
        int c32  = cid & 31;
        int slab = c32 >> 2, chunk = c32 & 3;
        uint4 v = *(const uint4*)&g_patch16[(m0 + row) * DDIM + slab * 32 + chunk * 8];
        *(uint4*)((char*)Xs + slab * 8192 + sw_off(row, chunk)) = v;
    }

    // ---- C streaming state: 2 chunks (16B) per thread per slab ----
    int r0 = tid >> 2,  g0 = tid & 3;
    int r1 = r0 + 64;
    uint32_t so0 = sw_off(r0, g0), so1 = sw_off(r1, g0);

    uint4 pc0, pc1;
    auto glob_loadC = [&](int ls) {
        int k0 = (ls & 7) * 32;
        int n0 = (ls >> 3) << 7;
        pc0 = *(const uint4*)&g_cb16[(n0 + r0) * DDIM + k0 + g0 * 8];
        pc1 = *(const uint4*)&g_cb16[(n0 + r1) * DDIM + k0 + g0 * 8];
    };
    auto stsC = [&](int buf) {
        *(uint4*)((char*)Cs + buf * 8192 + so0) = pc0;
        *(uint4*)((char*)Cs + buf * 8192 + so1) = pc1;
    };

    // LDSM invariants
    int arow[2], brow[4];
    #pragma unroll
    for (int mt = 0; mt < 2; ++mt) arow[mt] = wm * 32 + mt * 16 + (lane & 15);
    #pragma unroll
    for (int nt = 0; nt < 4; ++nt) brow[nt] = wn * 64 + nt * 16 + (lane & 15);
    int ch_hi = lane >> 4;

    float acc[2][8][4];
    glob_loadC(0);
    stsC(0);                  // slab 0 -> buf 0 (published by first sync)
    glob_loadC(1);

    for (int ls = 0; ls < 64; ++ls) {
        int s   = ls & 7;
        int buf = ls & 1;
        if (ls > 0) stsC(buf);         // regs hold slab ls (loaded at iter ls-1)
        __syncthreads();               // publish slab ls (and X on ls==0)
        if (s == 0) {
            // init accumulators to -cn/2 (fold cnorm into the GEMM)
            #pragma unroll
            for (int nt = 0; nt < 8; ++nt)
                #pragma unroll
                for (int z = 0; z < 4; ++z) {
                    int nloc = wn * 64 + nt * 8 + 2 * (lane & 3) + (z & 1);
                    float v = -0.5f * cn_sh[nloc];
                    acc[0][nt][z] = v;
                    acc[1][nt][z] = v;
                }
        }
        if (ls < 63) glob_loadC(ls + 1);   // prefetch next slab into regs

        uint32_t xslab = xs_base + (uint32_t)(s * 8192);
        #pragma unroll
        for (int kstep = 0; kstep < 2; ++kstep) {
            int kc = kstep * 2 + ch_hi;
            uint32_t a[2][4];
            #pragma unroll
            for (int mt = 0; mt < 2; ++mt)
                ldsm_x4(a[mt], xslab + sw_off(arow[mt], kc));
            #pragma unroll
            for (int ntp = 0; ntp < 4; ++ntp) {
                uint32_t b[4];
                ldsm_x4(b, cs_base + (uint32_t)(buf * 8192) + sw_off(brow[ntp], kc));
                #pragma unroll
                for (int mt = 0; mt < 2; ++mt) {
                    mma_bf16(acc[mt][2 * ntp + 0], a[mt], b[0], b[2]);
                    mma_bf16(acc[mt][2 * ntp + 1], a[mt], b[1], b[3]);
                }
            }
        }

        if (s == 7) {
            int nchunk0 = (ls >> 3) << 7;
            // ---- epilogue: running max + loose candidate collection ----
            // acc[mt][nt][2h+col]:
            //   row  = wm*32 + mt*16 + (lane>>2) + 8h
            //   code = nchunk0 + wn*64 + nt*8 + 2*(lane&3) + col
            #pragma unroll
            for (int mt = 0; mt < 2; ++mt)
                #pragma unroll
                for (int h = 0; h < 2; ++h) {
                    int mloc = wm * 32 + mt * 16 + (lane >> 2) + 8 * h;
                    float mv = acc[mt][0][2 * h];
                    #pragma unroll
                    for (int nt = 0; nt < 8; ++nt) {
                        mv = fmaxf(mv, acc[mt][nt][2 * h + 0]);
                        mv = fmaxf(mv, acc[mt][nt][2 * h + 1]);
                    }
                    mv = fmaxf(mv, __shfl_xor_sync(0xffffffffu, mv, 1));
                    mv = fmaxf(mv, __shfl_xor_sync(0xffffffffu, mv, 2));
                    if ((lane & 3) == 0) atomicMax(&smax[mloc], encf(mv));
                }
            __syncthreads();
            #pragma unroll
            for (int mt = 0; mt < 2; ++mt)
                #pragma unroll
                for (int h = 0; h < 2; ++h) {
                    int mloc = wm * 32 + mt * 16 + (lane >> 2) + 8 * h;
                    float lim = decf(smax[mloc]) - THRESH_DOT;
                    #pragma unroll
                    for (int nt = 0; nt < 8; ++nt)
                        #pragma unroll
                        for (int col = 0; col < 2; ++col) {
                            float v = acc[mt][nt][2 * h + col];
                            if (v >= lim) {
                                int code = nchunk0 + wn * 64 + nt * 8 + 2 * (lane & 3) + col;
                                int p = atomicAdd(&cnt[mloc], 1);
                                if (p < SLOTS) slots[mloc * SLOTS + p] = (short)code;
                            }
                        }
                }
            // prefetch next chunk's cnorm (ordered by next top-of-loop sync)
            if (ls < 63 && tid < 128) cn_sh[tid] = g_cnorm[nchunk0 + 128 + tid];
        }
    }
    __syncthreads();
    if (tid < 128) g_ccnt[m0 + tid] = cnt[tid];
    for (int i = tid; i < 128 * SLOTS; i += 256)
        g_cand[(m0 + i / SLOTS) * SLOTS + (i % SLOTS)] = slots[i];
}

// ---------------------------------------------------------------------------
// K3 (Phase B): exact fp32 rescore. One warp per row; 32 lanes split 256 dims.
// x gathered directly from the original NCHW layout (dim d = c*16+py*4+px:
// lane covers c=lane/2, py=(lane&1)*2 + {0,1} -> two float4 at stride 64).
// Fast path: c==1 -> bmu = the unique candidate, zero codebook traffic.
// v = fl(fl(xn - 2s) + cn), lowest-code tie-break (order-independent).
// ---------------------------------------------------------------------------
__global__ __launch_bounds__(256) void k_rescore(const float* __restrict__ x,
                                                 const float* __restrict__ cb) {
    int wid  = threadIdx.x >> 5;
    int lane = threadIdx.x & 31;
    int row  = blockIdx.x * 8 + wid;

    int c = g_ccnt[row];
    if (c == 1) {
        if (lane == 0) g_bmu[row] = g_cand[row * SLOTS];
        return;
    }

    int n = row >> 8, rem = row & 255;
    int ph = rem >> 4, pw = rem & 15;
    int cc = lane >> 1, pyb = (lane & 1) << 1;
    const float* xb = &x[(((n * 16 + cc) * 64 + ph * 4 + pyb) * 64 + pw * 4)];
    float4 x0 = *(const float4*)xb;          // dims lane*8 .. +3
    float4 x1 = *(const float4*)(xb + 64);   // dims lane*8+4 .. +7

    float xn = g_xnorm[row];
    float bv = __int_as_float(0x7f800000);
    int   bi = 0x7fffffff;

    bool ovf = (c > SLOTS);
    int  lim = ovf ? KCODES : c;

    for (int p = 0; p < lim; p += 4) {
        int codes[4];
        float s[4];
        #pragma unroll
        for (int j = 0; j < 4; ++j) {
            int pp = (p + j < lim) ? (p + j) : (lim - 1);
            codes[j] = ovf ? pp : (int)g_cand[row * SLOTS + pp];
        }
        #pragma unroll
        for (int j = 0; j < 4; ++j) {
            float4 c0 = *(const float4*)&cb[codes[j] * DDIM + lane * 8];
            float4 c1 = *(const float4*)&cb[codes[j] * DDIM + lane * 8 + 4];
            float t = x0.x * c0.x;
            t = fmaf(x0.y, c0.y, t); t = fmaf(x0.z, c0.z, t); t = fmaf(x0.w, c0.w, t);
            t = fmaf(x1.x, c1.x, t); t = fmaf(x1.y, c1.y, t);
            t = fmaf(x1.z, c1.z, t); t = fmaf(x1.w, c1.w, t);
            s[j] = t;
        }
        #pragma unroll
        for (int o = 16; o; o >>= 1)
            #pragma unroll
            for (int j = 0; j < 4; ++j)
                s[j] += __shfl_xor_sync(0xffffffffu, s[j], o);
        #pragma unroll
        for (int j = 0; j < 4; ++j) {
            if (p + j < lim) {
                float v = __fadd_rn(__fmaf_rn(-2.0f, s[j], xn), g_cnorm[codes[j]]);
                if (v < bv || (v == bv && codes[j] < bi)) { bv = v; bi = codes[j]; }
            }
        }
    }
    if (lane == 0) g_bmu[row] = bi;
}

// ---------------------------------------------------------------------------
// K4: gather smoothed[bmu] -> output, float4 vectorized (d%4==0 aligned)
// ---------------------------------------------------------------------------
__global__ void k_output(float* __restrict__ out) {
    int e = blockIdx.x * blockDim.x + threadIdx.x;   // one float4 per thread
    int idx = e * 4;
    int w = idx & 63;
    int h = (idx >> 6) & 63;
    int c = (idx >> 12) & 15;
    int n = idx >> 16;
    int i = (n << 8) + ((h >> 2) << 4) + (w >> 2);
    int d = (c << 4) + ((h & 3) << 2);               // w&3 spans the float4
    float4 v = *(const float4*)&g_smooth[g_bmu[i] * DDIM + d];
    *(float4*)&out[idx] = v;
}

// ---------------------------------------------------------------------------
extern "C" void kernel_launch(void* const* d_in, const int* in_sizes, int n_in,
                              void* d_out, int out_size) {
    const float* x  = (const float*)d_in[0];   // (128,16,64,64)
    const float* cb = (const float*)d_in[1];   // (1024,256)
    float* out = (float*)d_out;

    cudaFuncSetAttribute(k_prune, cudaFuncAttributeMaxDynamicSharedMemorySize,
                         SM_TOTAL);

    k_patchify<<<NPATCH / 4, 256>>>(x);
    k_cbprep <<<128 + KCODES / 4, 256>>>(cb);
    k_prune  <<<NPATCH / 128, 256, SM_TOTAL>>>();
    k_rescore<<<NPATCH / 8, 256>>>(x, cb);
    k_output <<<NPATCH * DDIM / 1024, 256>>>(out);
}

// round 11
// speedup vs baseline: 7.2608x; 1.1783x over previous
#include <cuda_runtime.h>
#include <cuda_bf16.h>
#include <cstdint>

// Problem constants
#define NPATCH   32768      // 128 batch * 16*16 patches
#define DDIM     256        // 16 channels * 4*4 patch
#define KCODES   1024
// 1/(2*variance) with variance = -(256 / (2*ln 0.1))  =>  inv2var = ln(10)/256
#define INV2VAR  0.0089944730195076785f
#define SLOTS    28
#define TH_COLLECT 8e-4f    // collection window vs running max
#define TH_FINAL   5e-4f    // refilter window vs final max (2B bound, ~8 sigma)

// Scratch (static device globals; no runtime allocation)
__device__ __nv_bfloat16  g_patch16[NPATCH * DDIM];  // bf16 patches (tensor prune)
__device__ __nv_bfloat16  g_cb16  [KCODES * DDIM];
__device__ float          g_xnorm [NPATCH];
__device__ float          g_cnorm [KCODES];
__device__ float          g_smooth[KCODES * DDIM];
__device__ int            g_bmu   [NPATCH];

// ---- monotone float<->uint encoding for atomicMax over floats -------------
__device__ __forceinline__ unsigned encf(float f) {
    unsigned u = __float_as_uint(f);
    return (u & 0x80000000u) ? ~u : (u | 0x80000000u);
}
__device__ __forceinline__ float decf(unsigned u) {
    u = (u & 0x80000000u) ? (u & 0x7fffffffu) : ~u;
    return __uint_as_float(u);
}

// ---- tensor-core primitives ----------------------------------------------
__device__ __forceinline__ void ldsm_x4(uint32_t (&r)[4], uint32_t saddr) {
    asm volatile("ldmatrix.sync.aligned.m8n8.x4.shared.b16 {%0,%1,%2,%3}, [%4];"
                 : "=r"(r[0]), "=r"(r[1]), "=r"(r[2]), "=r"(r[3]) : "r"(saddr));
}
__device__ __forceinline__ void mma_bf16(float (&d)[4], const uint32_t (&a)[4],
                                         uint32_t b0, uint32_t b1) {
    asm volatile("mma.sync.aligned.m16n8k16.row.col.f32.bf16.bf16.f32 "
                 "{%0,%1,%2,%3}, {%4,%5,%6,%7}, {%8,%9}, {%0,%1,%2,%3};"
                 : "+f"(d[0]), "+f"(d[1]), "+f"(d[2]), "+f"(d[3])
                 : "r"(a[0]), "r"(a[1]), "r"(a[2]), "r"(a[3]), "r"(b0), "r"(b1));
}

// XOR swizzle for 64B-row smem tiles: chunk' = chunk ^ ((row>>1)&3).
// Conflict-free for STS.128 and LDSM.
__device__ __forceinline__ uint32_t sw_off(int row, int chunk) {
    return (uint32_t)(row * 64 + ((chunk ^ ((row >> 1) & 3)) << 4));
}

// dynamic-smem layout for k_prune (bytes)
#define SM_XS     0          // [8][128*32] bf16  = 65536
#define SM_CS     65536      // [2][128*32] bf16  = 16384
#define SM_CN     81920      // float[128]     -> 82432
#define SM_MAX    82432      // unsigned[128]  -> 82944
#define SM_CNT    82944      // int[128]       -> 83456
#define SM_SLOTV  83456      // float[128*28] = 14336 -> 97792
#define SM_SLOTC  97792      // short[128*28] =  7168 -> 104960
#define SM_Q      104960     // int[128]       -> 105472
#define SM_QN     105472     // int[2] (qcount, qhead) -> 105480
#define SM_TOTAL  105600

// ---------------------------------------------------------------------------
// K0: merged prep.
// Blocks [0, 8192): patchify -> bf16 + per-patch norm (4 patches / block).
// Blocks [8192, 8320): cnorm + bf16 codebook copy (one warp per row).
// Blocks [8320, 8576): Gaussian-smoothed codebook (4 rows / block).
// ---------------------------------------------------------------------------
__global__ void k_prep(const float* __restrict__ x, const float* __restrict__ cb) {
    int tid = threadIdx.x;
    if (blockIdx.x < 8192) {
        __shared__ float red[4][2];
        int t   = tid & 63;
        int sub = tid >> 6;
        int i = blockIdx.x * 4 + sub;
        int n = i >> 8, rem = i & 255;
        int ph = rem >> 4, pw = rem & 15;
        int c = t >> 2, py = t & 3;
        float4 v = *(const float4*)&x[(((n * 16 + c) * 64 + ph * 4 + py) * 64 + pw * 4)];
        int dst = i * DDIM + c * 16 + py * 4;
        __nv_bfloat162 b01 = __floats2bfloat162_rn(v.x, v.y);
        __nv_bfloat162 b23 = __floats2bfloat162_rn(v.z, v.w);
        *(__nv_bfloat162*)&g_patch16[dst]     = b01;
        *(__nv_bfloat162*)&g_patch16[dst + 2] = b23;
        float s = fmaf(v.x, v.x, fmaf(v.y, v.y, fmaf(v.z, v.z, v.w * v.w)));
        #pragma unroll
        for (int o = 16; o; o >>= 1) s += __shfl_xor_sync(0xffffffffu, s, o);
        if ((t & 31) == 0) red[sub][t >> 5] = s;
        __syncthreads();
        if (t == 0) g_xnorm[i] = red[sub][0] + red[sub][1];
    } else if (blockIdx.x < 8320) {
        int row  = (blockIdx.x - 8192) * 8 + (tid >> 5);
        int lane = tid & 31;
        const float* p = cb + row * DDIM;
        float s = 0.0f;
        #pragma unroll
        for (int j = 0; j < DDIM / 32; ++j) {
            float v = p[lane + j * 32];
            g_cb16[row * DDIM + lane + j * 32] = __float2bfloat16(v);
            s = fmaf(v, v, s);
        }
        #pragma unroll
        for (int o = 16; o; o >>= 1) s += __shfl_xor_sync(0xffffffffu, s, o);
        if (lane == 0) g_cnorm[row] = s;
    } else {
        __shared__ float wd[136];
        int jbase = (blockIdx.x - 8320) * 4;
        if (tid < 136) {
            float dd = (float)(tid - 67);
            wd[tid] = expf(-(dd * dd) * INV2VAR);
        }
        __syncthreads();
        float acc[4] = {0.f, 0.f, 0.f, 0.f};
        int klo = jbase - 64;      if (klo < 0) klo = 0;
        int khi = jbase + 3 + 64;  if (khi > KCODES - 1) khi = KCODES - 1;
        for (int kk = klo; kk <= khi; ++kk) {
            float v = cb[kk * DDIM + tid];
            int base = kk - jbase + 67;
            #pragma unroll
            for (int t = 0; t < 4; ++t)
                acc[t] = fmaf(wd[base - t], v, acc[t]);
        }
        #pragma unroll
        for (int t = 0; t < 4; ++t)
            g_smooth[(jbase + t) * DDIM + tid] = acc[t];
    }
}

// ---------------------------------------------------------------------------
// K1: fused prune + refilter + exact rescore.
// Phase A: bf16 MMA over 128 rows x 1024 codes; candidates (value, code)
//   collected within TH_COLLECT of the running per-row max.
// Phase B: refilter vs FINAL max with TH_FINAL (superset proof: running max
//   <= final max and TH_COLLECT >= TH_FINAL). Rows with one survivor -> bmu
//   directly. Rows with >=2 (or overflow) go to a smem work queue consumed
//   by all 8 warps (load-balanced exact fp32 rescore, reference rounding
//   chain + lowest-code tie-break).
// ---------------------------------------------------------------------------
__global__ __launch_bounds__(256, 2) void k_prune(const float* __restrict__ x,
                                                  const float* __restrict__ cb) {
    extern __shared__ char smem_raw[];
    __nv_bfloat16* Xs    = (__nv_bfloat16*)(smem_raw + SM_XS);
    __nv_bfloat16* Cs    = (__nv_bfloat16*)(smem_raw + SM_CS);
    float*    cn_sh  = (float*)   (smem_raw + SM_CN);
    unsigned* smax   = (unsigned*)(smem_raw + SM_MAX);
    int*      cnt    = (int*)     (smem_raw + SM_CNT);
    float*    slot_v = (float*)   (smem_raw + SM_SLOTV);
    short*    slot_c = (short*)   (smem_raw + SM_SLOTC);
    int*      queue  = (int*)     (smem_raw + SM_Q);
    int*      qn     = (int*)     (smem_raw + SM_QN);   // [0]=count, [1]=head

    int tid  = threadIdx.x;
    int lane = tid & 31;
    int wid  = tid >> 5;
    int wm   = wid & 3;            // m band: 32 rows
    int wn   = wid >> 2;           // n band: 64 codes
    int m0   = blockIdx.x * 128;

    if (tid < 128) { smax[tid] = 0u; cnt[tid] = 0; cn_sh[tid] = g_cnorm[tid]; }
    if (tid == 0) { qn[0] = 0; qn[1] = 0; }

    uint32_t xs_base = (uint32_t)__cvta_generic_to_shared(Xs);
    uint32_t cs_base = (uint32_t)__cvta_generic_to_shared(Cs);

    // ---- load resident X tile: 4096 16B-chunks, coalesced ----
    #pragma unroll
    for (int i = 0; i < 16; ++i) {
        int cid  = i * 256 + tid;
        int row  = cid >> 5;
        int c32  = cid & 31;
        int slab = c32 >> 2, chunk = c32 & 3;
        uint4 v = *(const uint4*)&g_patch16[(m0 + row) * DDIM + slab * 32 + chunk * 8];
        *(uint4*)((char*)Xs + slab * 8192 + sw_off(row, chunk)) = v;
    }

    // ---- C streaming: 2 chunks (16B) per thread per slab ----
    int r0 = tid >> 2,  g0 = tid & 3;
    int r1 = r0 + 64;
    uint32_t so0 = sw_off(r0, g0), so1 = sw_off(r1, g0);

    uint4 pc0, pc1;
    auto glob_loadC = [&](int ls) {
        int k0 = (ls & 7) * 32;
        int n0 = (ls >> 3) << 7;
        pc0 = *(const uint4*)&g_cb16[(n0 + r0) * DDIM + k0 + g0 * 8];
        pc1 = *(const uint4*)&g_cb16[(n0 + r1) * DDIM + k0 + g0 * 8];
    };
    auto stsC = [&](int buf) {
        *(uint4*)((char*)Cs + buf * 8192 + so0) = pc0;
        *(uint4*)((char*)Cs + buf * 8192 + so1) = pc1;
    };

    // LDSM invariants
    int arow[2], brow[4];
    #pragma unroll
    for (int mt = 0; mt < 2; ++mt) arow[mt] = wm * 32 + mt * 16 + (lane & 15);
    #pragma unroll
    for (int nt = 0; nt < 4; ++nt) brow[nt] = wn * 64 + nt * 16 + (lane & 15);
    int ch_hi = lane >> 4;

    float acc[2][8][4];
    glob_loadC(0);
    stsC(0);
    glob_loadC(1);

    for (int ls = 0; ls < 64; ++ls) {
        int s   = ls & 7;
        int buf = ls & 1;
        if (ls > 0) stsC(buf);
        __syncthreads();
        if (s == 0) {
            #pragma unroll
            for (int nt = 0; nt < 8; ++nt)
                #pragma unroll
                for (int z = 0; z < 4; ++z) {
                    int nloc = wn * 64 + nt * 8 + 2 * (lane & 3) + (z & 1);
                    float v = -0.5f * cn_sh[nloc];
                    acc[0][nt][z] = v;
                    acc[1][nt][z] = v;
                }
        }
        if (ls < 63) glob_loadC(ls + 1);

        uint32_t xslab = xs_base + (uint32_t)(s * 8192);
        #pragma unroll
        for (int kstep = 0; kstep < 2; ++kstep) {
            int kc = kstep * 2 + ch_hi;
            uint32_t a[2][4];
            #pragma unroll
            for (int mt = 0; mt < 2; ++mt)
                ldsm_x4(a[mt], xslab + sw_off(arow[mt], kc));
            #pragma unroll
            for (int ntp = 0; ntp < 4; ++ntp) {
                uint32_t b[4];
                ldsm_x4(b, cs_base + (uint32_t)(buf * 8192) + sw_off(brow[ntp], kc));
                #pragma unroll
                for (int mt = 0; mt < 2; ++mt) {
                    mma_bf16(acc[mt][2 * ntp + 0], a[mt], b[0], b[2]);
                    mma_bf16(acc[mt][2 * ntp + 1], a[mt], b[1], b[3]);
                }
            }
        }

        if (s == 7) {
            int nchunk0 = (ls >> 3) << 7;
            // running max update
            #pragma unroll
            for (int mt = 0; mt < 2; ++mt)
                #pragma unroll
                for (int h = 0; h < 2; ++h) {
                    int mloc = wm * 32 + mt * 16 + (lane >> 2) + 8 * h;
                    float mv = acc[mt][0][2 * h];
                    #pragma unroll
                    for (int nt = 0; nt < 8; ++nt) {
                        mv = fmaxf(mv, acc[mt][nt][2 * h + 0]);
                        mv = fmaxf(mv, acc[mt][nt][2 * h + 1]);
                    }
                    mv = fmaxf(mv, __shfl_xor_sync(0xffffffffu, mv, 1));
                    mv = fmaxf(mv, __shfl_xor_sync(0xffffffffu, mv, 2));
                    if ((lane & 3) == 0) atomicMax(&smax[mloc], encf(mv));
                }
            __syncthreads();
            // collect (value, code) within TH_COLLECT of running max
            #pragma unroll
            for (int mt = 0; mt < 2; ++mt)
                #pragma unroll
                for (int h = 0; h < 2; ++h) {
                    int mloc = wm * 32 + mt * 16 + (lane >> 2) + 8 * h;
                    float lim = decf(smax[mloc]) - TH_COLLECT;
                    #pragma unroll
                    for (int nt = 0; nt < 8; ++nt)
                        #pragma unroll
                        for (int col = 0; col < 2; ++col) {
                            float v = acc[mt][nt][2 * h + col];
                            if (v >= lim) {
                                int code = nchunk0 + wn * 64 + nt * 8 + 2 * (lane & 3) + col;
                                int p = atomicAdd(&cnt[mloc], 1);
                                if (p < SLOTS) {
                                    slot_v[mloc * SLOTS + p] = v;
                                    slot_c[mloc * SLOTS + p] = (short)code;
                                }
                            }
                        }
                }
        }
    }
    __syncthreads();

    // ---- Phase B1: refilter vs final max; warp wid owns rows wid*16..+15 ----
    for (int rr = 0; rr < 16; ++rr) {
        int mloc = wid * 16 + rr;
        int craw = cnt[mloc];
        bool of  = (craw > SLOTS);
        int base = mloc * SLOTS;
        if (of) {
            if (lane == 0) { int q = atomicAdd(&qn[0], 1); queue[q] = mloc; }
            continue;
        }
        float lim = decf(smax[mloc]) - TH_FINAL;
        bool keep = (lane < craw) && (slot_v[base + lane] >= lim);
        unsigned m = __ballot_sync(0xffffffffu, keep);
        short mycode = keep ? slot_c[base + lane] : 0;
        int pos = __popc(m & ((1u << lane) - 1));
        __syncwarp();
        if (keep) slot_c[base + pos] = mycode;
        __syncwarp();
        int nkeep = __popc(m);
        if (lane == 0) {
            if (nkeep == 1) {
                g_bmu[m0 + mloc] = slot_c[base];
            } else {
                cnt[mloc] = nkeep;
                int q = atomicAdd(&qn[0], 1); queue[q] = mloc;
            }
        }
    }
    __syncthreads();

    // ---- Phase B2: load-balanced exact fp32 rescore of queued rows ----
    int qcount = qn[0];
    for (;;) {
        int t;
        if (lane == 0) t = atomicAdd(&qn[1], 1);
        t = __shfl_sync(0xffffffffu, t, 0);
        if (t >= qcount) break;
        int mloc = queue[t];
        int row  = m0 + mloc;
        int c    = cnt[mloc];
        bool ovf = (c > SLOTS);
        int  lim = ovf ? KCODES : c;
        int base = mloc * SLOTS;

        // gather fp32 x from original NCHW layout (dims lane*8 .. lane*8+7)
        int n = row >> 8, rem = row & 255;
        int ph = rem >> 4, pw = rem & 15;
        int cc = lane >> 1, pyb = (lane & 1) << 1;
        const float* xb = &x[(((n * 16 + cc) * 64 + ph * 4 + pyb) * 64 + pw * 4)];
        float4 x0 = *(const float4*)xb;
        float4 x1 = *(const float4*)(xb + 64);

        float xn = g_xnorm[row];
        float bv = __int_as_float(0x7f800000);
        int   bi = 0x7fffffff;

        for (int p = 0; p < lim; p += 4) {
            int codes[4];
            float s[4];
            #pragma unroll
            for (int j = 0; j < 4; ++j) {
                int pp = (p + j < lim) ? (p + j) : (lim - 1);
                codes[j] = ovf ? pp : (int)slot_c[base + pp];
            }
            #pragma unroll
            for (int j = 0; j < 4; ++j) {
                float4 c0 = *(const float4*)&cb[codes[j] * DDIM + lane * 8];
                float4 c1 = *(const float4*)&cb[codes[j] * DDIM + lane * 8 + 4];
                float t2 = x0.x * c0.x;
                t2 = fmaf(x0.y, c0.y, t2); t2 = fmaf(x0.z, c0.z, t2); t2 = fmaf(x0.w, c0.w, t2);
                t2 = fmaf(x1.x, c1.x, t2); t2 = fmaf(x1.y, c1.y, t2);
                t2 = fmaf(x1.z, c1.z, t2); t2 = fmaf(x1.w, c1.w, t2);
                s[j] = t2;
            }
            #pragma unroll
            for (int o = 16; o; o >>= 1)
                #pragma unroll
                for (int j = 0; j < 4; ++j)
                    s[j] += __shfl_xor_sync(0xffffffffu, s[j], o);
            #pragma unroll
            for (int j = 0; j < 4; ++j) {
                if (p + j < lim) {
                    float v = __fadd_rn(__fmaf_rn(-2.0f, s[j], xn), g_cnorm[codes[j]]);
                    if (v < bv || (v == bv && codes[j] < bi)) { bv = v; bi = codes[j]; }
                }
            }
        }
        if (lane == 0) g_bmu[row] = bi;
    }
}

// ---------------------------------------------------------------------------
// K2: gather smoothed[bmu] -> output, float4 vectorized (d%4==0 aligned)
// ---------------------------------------------------------------------------
__global__ void k_output(float* __restrict__ out) {
    int e = blockIdx.x * blockDim.x + threadIdx.x;   // one float4 per thread
    int idx = e * 4;
    int w = idx & 63;
    int h = (idx >> 6) & 63;
    int c = (idx >> 12) & 15;
    int n = idx >> 16;
    int i = (n << 8) + ((h >> 2) << 4) + (w >> 2);
    int d = (c << 4) + ((h & 3) << 2);               // w&3 spans the float4
    float4 v = *(const float4*)&g_smooth[g_bmu[i] * DDIM + d];
    *(float4*)&out[idx] = v;
}

// ---------------------------------------------------------------------------
extern "C" void kernel_launch(void* const* d_in, const int* in_sizes, int n_in,
                              void* d_out, int out_size) {
    const float* x  = (const float*)d_in[0];   // (128,16,64,64)
    const float* cb = (const float*)d_in[1];   // (1024,256)
    float* out = (float*)d_out;

    cudaFuncSetAttribute(k_prune, cudaFuncAttributeMaxDynamicSharedMemorySize,
                         SM_TOTAL);

    k_prep  <<<8192 + 128 + 256, 256>>>(x, cb);
    k_prune <<<NPATCH / 128, 256, SM_TOTAL>>>(x, cb);
    k_output<<<NPATCH * DDIM / 1024, 256>>>(out);
}

// round 13
// speedup vs baseline: 7.4260x; 1.0228x over previous
#include <cuda_runtime.h>
#include <cuda_bf16.h>
#include <cstdint>

// Problem constants
#define NPATCH   32768      // 128 batch * 16*16 patches
#define DDIM     256        // 16 channels * 4*4 patch
#define KCODES   1024
// 1/(2*variance) with variance = -(256 / (2*ln 0.1))  =>  inv2var = ln(10)/256
#define INV2VAR  0.0089944730195076785f
#define SLOTS    28
#define TH_COLLECT 8e-4f    // collection window vs running max
#define TH_FINAL   5e-4f    // refilter window vs final max

// Scratch (static device globals; no runtime allocation)
__device__ __nv_bfloat16  g_cb16  [KCODES * DDIM];
__device__ float          g_cnorm [KCODES];
__device__ float          g_smooth[KCODES * DDIM];
__device__ int            g_bmu   [NPATCH];

// ---- bit-cast helper (no __bfloat162_as_uint in this toolkit) -------------
__device__ __forceinline__ uint32_t bf2_bits(__nv_bfloat162 v) {
    union { __nv_bfloat162 h; uint32_t u; } cv;
    cv.h = v;
    return cv.u;
}

// ---- monotone float<->uint encoding for atomicMax over floats -------------
__device__ __forceinline__ unsigned encf(float f) {
    unsigned u = __float_as_uint(f);
    return (u & 0x80000000u) ? ~u : (u | 0x80000000u);
}
__device__ __forceinline__ float decf(unsigned u) {
    u = (u & 0x80000000u) ? (u & 0x7fffffffu) : ~u;
    return __uint_as_float(u);
}

// ---- tensor-core primitives ----------------------------------------------
__device__ __forceinline__ void ldsm_x4(uint32_t (&r)[4], uint32_t saddr) {
    asm volatile("ldmatrix.sync.aligned.m8n8.x4.shared.b16 {%0,%1,%2,%3}, [%4];"
                 : "=r"(r[0]), "=r"(r[1]), "=r"(r[2]), "=r"(r[3]) : "r"(saddr));
}
__device__ __forceinline__ void mma_bf16(float (&d)[4], const uint32_t (&a)[4],
                                         uint32_t b0, uint32_t b1) {
    asm volatile("mma.sync.aligned.m16n8k16.row.col.f32.bf16.bf16.f32 "
                 "{%0,%1,%2,%3}, {%4,%5,%6,%7}, {%8,%9}, {%0,%1,%2,%3};"
                 : "+f"(d[0]), "+f"(d[1]), "+f"(d[2]), "+f"(d[3])
                 : "r"(a[0]), "r"(a[1]), "r"(a[2]), "r"(a[3]), "r"(b0), "r"(b1));
}

// XOR swizzle for 64B-row smem tiles: chunk' = chunk ^ ((row>>1)&3).
// Conflict-free for LDSM; used consistently on store and load side.
__device__ __forceinline__ uint32_t sw_off(int row, int chunk) {
    return (uint32_t)(row * 64 + ((chunk ^ ((row >> 1) & 3)) << 4));
}

// dynamic-smem layout for k_prune (bytes)
#define SM_XS     0          // [8][128*32] bf16  = 65536
#define SM_CS     65536      // [2][128*32] bf16  = 16384
#define SM_CN     81920      // float[128]     -> 82432
#define SM_MAX    82432      // unsigned[128]  -> 82944
#define SM_CNT    82944      // int[128]       -> 83456
#define SM_SLOTV  83456      // float[128*28] = 14336 -> 97792
#define SM_SLOTC  97792      // short[128*28] =  7168 -> 104960
#define SM_Q      104960     // int[128]       -> 105472
#define SM_QN     105472     // int[2] (qcount, qhead)
#define SM_XN     105480     // float[128] xnorm -> 105992
#define SM_TOTAL  106112

// ---------------------------------------------------------------------------
// K0: codebook prep only.
// Blocks [0,128): cnorm + bf16 copy (one warp per row).
// Blocks [128,384): Gaussian-smoothed codebook (4 rows/block, radius-64).
// ---------------------------------------------------------------------------
__global__ void k_prep(const float* __restrict__ cb) {
    int tid = threadIdx.x;
    if (blockIdx.x < 128) {
        int row  = blockIdx.x * 8 + (tid >> 5);
        int lane = tid & 31;
        const float* p = cb + row * DDIM;
        float s = 0.0f;
        #pragma unroll
        for (int j = 0; j < DDIM / 32; ++j) {
            float v = p[lane + j * 32];
            g_cb16[row * DDIM + lane + j * 32] = __float2bfloat16(v);
            s = fmaf(v, v, s);
        }
        #pragma unroll
        for (int o = 16; o; o >>= 1) s += __shfl_xor_sync(0xffffffffu, s, o);
        if (lane == 0) g_cnorm[row] = s;
    } else {
        __shared__ float wd[136];
        int jbase = (blockIdx.x - 128) * 4;
        if (tid < 136) {
            float dd = (float)(tid - 67);
            wd[tid] = expf(-(dd * dd) * INV2VAR);
        }
        __syncthreads();
        float acc[4] = {0.f, 0.f, 0.f, 0.f};
        int klo = jbase - 64;      if (klo < 0) klo = 0;
        int khi = jbase + 3 + 64;  if (khi > KCODES - 1) khi = KCODES - 1;
        for (int kk = klo; kk <= khi; ++kk) {
            float v = cb[kk * DDIM + tid];
            int base = kk - jbase + 67;
            #pragma unroll
            for (int t = 0; t < 4; ++t)
                acc[t] = fmaf(wd[base - t], v, acc[t]);
        }
        #pragma unroll
        for (int t = 0; t < 4; ++t)
            g_smooth[(jbase + t) * DDIM + tid] = acc[t];
    }
}

// ---------------------------------------------------------------------------
// K1: fused patchify + prune + refilter + exact rescore.
// X tile (this CTA's 128 patches) is read from x (fp32 NCHW) ONCE, converted
// to bf16 straight into swizzled smem; per-row xnorm via warp butterfly.
// Phase A: bf16 MMA over 128 rows x 1024 codes (acc init -cnorm/2);
//   candidates within TH_COLLECT of the running per-row max.
// Phase B: refilter vs FINAL max (TH_FINAL); single survivor -> bmu; else
//   smem work queue, all 8 warps run exact fp32 rescore (reference rounding
//   chain fl(fl(xn-2s)+cn) + lowest-code tie-break).
// ---------------------------------------------------------------------------
__global__ __launch_bounds__(256, 2) void k_prune(const float* __restrict__ x,
                                                  const float* __restrict__ cb) {
    extern __shared__ char smem_raw[];
    __nv_bfloat16* Xs    = (__nv_bfloat16*)(smem_raw + SM_XS);
    __nv_bfloat16* Cs    = (__nv_bfloat16*)(smem_raw + SM_CS);
    float*    cn_sh  = (float*)   (smem_raw + SM_CN);
    unsigned* smax   = (unsigned*)(smem_raw + SM_MAX);
    int*      cnt    = (int*)     (smem_raw + SM_CNT);
    float*    slot_v = (float*)   (smem_raw + SM_SLOTV);
    short*    slot_c = (short*)   (smem_raw + SM_SLOTC);
    int*      queue  = (int*)     (smem_raw + SM_Q);
    int*      qn     = (int*)     (smem_raw + SM_QN);   // [0]=count, [1]=head
    float*    xn_sh  = (float*)   (smem_raw + SM_XN);

    int tid  = threadIdx.x;
    int lane = tid & 31;
    int wid  = tid >> 5;
    int wm   = wid & 3;            // m band: 32 rows
    int wn   = wid >> 2;           // n band: 64 codes
    int m0   = blockIdx.x * 128;

    if (tid < 128) { smax[tid] = 0u; cnt[tid] = 0; cn_sh[tid] = g_cnorm[tid]; }
    if (tid == 0) { qn[0] = 0; qn[1] = 0; }

    uint32_t xs_base = (uint32_t)__cvta_generic_to_shared(Xs);
    uint32_t cs_base = (uint32_t)__cvta_generic_to_shared(Cs);

    // ---- fused patchify: x fp32 -> bf16 Xs + xnorm. Per iteration i, each
    // warp owns one whole row (row = i*8 + wid), lane = 16B chunk (8 dims).
    #pragma unroll
    for (int i = 0; i < 16; ++i) {
        int row = i * 8 + wid;
        int m   = m0 + row;
        int n = m >> 8, rem = m & 255;
        int ph = rem >> 4, pw = rem & 15;
        int c = lane >> 1, pyb = (lane & 1) << 1;      // dims lane*8 .. +7
        const float* xb = &x[(((n * 16 + c) * 64 + ph * 4 + pyb) * 64 + pw * 4)];
        float4 a = *(const float4*)xb;
        float4 b = *(const float4*)(xb + 64);
        uint4 pk;
        pk.x = bf2_bits(__floats2bfloat162_rn(a.x, a.y));
        pk.y = bf2_bits(__floats2bfloat162_rn(a.z, a.w));
        pk.z = bf2_bits(__floats2bfloat162_rn(b.x, b.y));
        pk.w = bf2_bits(__floats2bfloat162_rn(b.z, b.w));
        int slab = lane >> 2, chunk = lane & 3;
        *(uint4*)((char*)Xs + slab * 8192 + sw_off(row, chunk)) = pk;
        float s = fmaf(a.x, a.x, fmaf(a.y, a.y, fmaf(a.z, a.z, a.w * a.w)));
        s = fmaf(b.x, b.x, fmaf(b.y, b.y, fmaf(b.z, b.z, fmaf(b.w, b.w, s))));
        #pragma unroll
        for (int o = 16; o; o >>= 1) s += __shfl_xor_sync(0xffffffffu, s, o);
        if (lane == 0) xn_sh[row] = s;
    }

    // ---- C streaming: 2 chunks (16B) per thread per slab ----
    int r0 = tid >> 2,  g0 = tid & 3;
    int r1 = r0 + 64;
    uint32_t so0 = sw_off(r0, g0), so1 = sw_off(r1, g0);

    uint4 pc0, pc1;
    auto glob_loadC = [&](int ls) {
        int k0 = (ls & 7) * 32;
        int n0 = (ls >> 3) << 7;
        pc0 = *(const uint4*)&g_cb16[(n0 + r0) * DDIM + k0 + g0 * 8];
        pc1 = *(const uint4*)&g_cb16[(n0 + r1) * DDIM + k0 + g0 * 8];
    };
    auto stsC = [&](int buf) {
        *(uint4*)((char*)Cs + buf * 8192 + so0) = pc0;
        *(uint4*)((char*)Cs + buf * 8192 + so1) = pc1;
    };

    // LDSM invariants
    int arow[2], brow[4];
    #pragma unroll
    for (int mt = 0; mt < 2; ++mt) arow[mt] = wm * 32 + mt * 16 + (lane & 15);
    #pragma unroll
    for (int nt = 0; nt < 4; ++nt) brow[nt] = wn * 64 + nt * 16 + (lane & 15);
    int ch_hi = lane >> 4;

    float acc[2][8][4];
    glob_loadC(0);
    stsC(0);
    glob_loadC(1);

    for (int ls = 0; ls < 64; ++ls) {
        int s   = ls & 7;
        int buf = ls & 1;
        if (ls > 0) stsC(buf);
        __syncthreads();               // publish slab ls (and X on ls==0)
        if (s == 0) {
            #pragma unroll
            for (int nt = 0; nt < 8; ++nt)
                #pragma unroll
                for (int z = 0; z < 4; ++z) {
                    int nloc = wn * 64 + nt * 8 + 2 * (lane & 3) + (z & 1);
                    float v = -0.5f * cn_sh[nloc];
                    acc[0][nt][z] = v;
                    acc[1][nt][z] = v;
                }
        }
        if (ls < 63) glob_loadC(ls + 1);

        uint32_t xslab = xs_base + (uint32_t)(s * 8192);
        #pragma unroll
        for (int kstep = 0; kstep < 2; ++kstep) {
            int kc = kstep * 2 + ch_hi;
            uint32_t a[2][4];
            #pragma unroll
            for (int mt = 0; mt < 2; ++mt)
                ldsm_x4(a[mt], xslab + sw_off(arow[mt], kc));
            #pragma unroll
            for (int ntp = 0; ntp < 4; ++ntp) {
                uint32_t b[4];
                ldsm_x4(b, cs_base + (uint32_t)(buf * 8192) + sw_off(brow[ntp], kc));
                #pragma unroll
                for (int mt = 0; mt < 2; ++mt) {
                    mma_bf16(acc[mt][2 * ntp + 0], a[mt], b[0], b[2]);
                    mma_bf16(acc[mt][2 * ntp + 1], a[mt], b[1], b[3]);
                }
            }
        }

        if (s == 7) {
            int nchunk0 = (ls >> 3) << 7;
            // running max update
            #pragma unroll
            for (int mt = 0; mt < 2; ++mt)
                #pragma unroll
                for (int h = 0; h < 2; ++h) {
                    int mloc = wm * 32 + mt * 16 + (lane >> 2) + 8 * h;
                    float mv = acc[mt][0][2 * h];
                    #pragma unroll
                    for (int nt = 0; nt < 8; ++nt) {
                        mv = fmaxf(mv, acc[mt][nt][2 * h + 0]);
                        mv = fmaxf(mv, acc[mt][nt][2 * h + 1]);
                    }
                    mv = fmaxf(mv, __shfl_xor_sync(0xffffffffu, mv, 1));
                    mv = fmaxf(mv, __shfl_xor_sync(0xffffffffu, mv, 2));
                    if ((lane & 3) == 0) atomicMax(&smax[mloc], encf(mv));
                }
            __syncthreads();
            // collect (value, code) within TH_COLLECT of running max
            #pragma unroll
            for (int mt = 0; mt < 2; ++mt)
                #pragma unroll
                for (int h = 0; h < 2; ++h) {
                    int mloc = wm * 32 + mt * 16 + (lane >> 2) + 8 * h;
                    float lim = decf(smax[mloc]) - TH_COLLECT;
                    #pragma unroll
                    for (int nt = 0; nt < 8; ++nt)
                        #pragma unroll
                        for (int col = 0; col < 2; ++col) {
                            float v = acc[mt][nt][2 * h + col];
                            if (v >= lim) {
                                int code = nchunk0 + wn * 64 + nt * 8 + 2 * (lane & 3) + col;
                                int p = atomicAdd(&cnt[mloc], 1);
                                if (p < SLOTS) {
                                    slot_v[mloc * SLOTS + p] = v;
                                    slot_c[mloc * SLOTS + p] = (short)code;
                                }
                            }
                        }
                }
        }
    }
    __syncthreads();

    // ---- Phase B1: refilter vs final max; warp wid owns rows wid*16..+15 ----
    for (int rr = 0; rr < 16; ++rr) {
        int mloc = wid * 16 + rr;
        int craw = cnt[mloc];
        bool of  = (craw > SLOTS);
        int base = mloc * SLOTS;
        if (of) {
            if (lane == 0) { int q = atomicAdd(&qn[0], 1); queue[q] = mloc; }
            continue;
        }
        float lim = decf(smax[mloc]) - TH_FINAL;
        bool keep = (lane < craw) && (slot_v[base + lane] >= lim);
        unsigned m = __ballot_sync(0xffffffffu, keep);
        short mycode = keep ? slot_c[base + lane] : 0;
        int pos = __popc(m & ((1u << lane) - 1));
        __syncwarp();
        if (keep) slot_c[base + pos] = mycode;
        __syncwarp();
        int nkeep = __popc(m);
        if (lane == 0) {
            if (nkeep == 1) {
                g_bmu[m0 + mloc] = slot_c[base];
            } else {
                cnt[mloc] = nkeep;
                int q = atomicAdd(&qn[0], 1); queue[q] = mloc;
            }
        }
    }
    __syncthreads();

    // ---- Phase B2: load-balanced exact fp32 rescore of queued rows ----
    int qcount = qn[0];
    for (;;) {
        int t;
        if (lane == 0) t = atomicAdd(&qn[1], 1);
        t = __shfl_sync(0xffffffffu, t, 0);
        if (t >= qcount) break;
        int mloc = queue[t];
        int row  = m0 + mloc;
        int c    = cnt[mloc];
        bool ovf = (c > SLOTS);
        int  lim = ovf ? KCODES : c;
        int base = mloc * SLOTS;

        // gather fp32 x from original NCHW layout (dims lane*8 .. lane*8+7)
        int n = row >> 8, rem = row & 255;
        int ph = rem >> 4, pw = rem & 15;
        int cc = lane >> 1, pyb = (lane & 1) << 1;
        const float* xb = &x[(((n * 16 + cc) * 64 + ph * 4 + pyb) * 64 + pw * 4)];
        float4 x0 = *(const float4*)xb;
        float4 x1 = *(const float4*)(xb + 64);

        float xn = xn_sh[mloc];
        float bv = __int_as_float(0x7f800000);
        int   bi = 0x7fffffff;

        for (int p = 0; p < lim; p += 4) {
            int codes[4];
            float s[4];
            #pragma unroll
            for (int j = 0; j < 4; ++j) {
                int pp = (p + j < lim) ? (p + j) : (lim - 1);
                codes[j] = ovf ? pp : (int)slot_c[base + pp];
            }
            #pragma unroll
            for (int j = 0; j < 4; ++j) {
                float4 c0 = *(const float4*)&cb[codes[j] * DDIM + lane * 8];
                float4 c1 = *(const float4*)&cb[codes[j] * DDIM + lane * 8 + 4];
                float t2 = x0.x * c0.x;
                t2 = fmaf(x0.y, c0.y, t2); t2 = fmaf(x0.z, c0.z, t2); t2 = fmaf(x0.w, c0.w, t2);
                t2 = fmaf(x1.x, c1.x, t2); t2 = fmaf(x1.y, c1.y, t2);
                t2 = fmaf(x1.z, c1.z, t2); t2 = fmaf(x1.w, c1.w, t2);
                s[j] = t2;
            }
            #pragma unroll
            for (int o = 16; o; o >>= 1)
                #pragma unroll
                for (int j = 0; j < 4; ++j)
                    s[j] += __shfl_xor_sync(0xffffffffu, s[j], o);
            #pragma unroll
            for (int j = 0; j < 4; ++j) {
                if (p + j < lim) {
                    float v = __fadd_rn(__fmaf_rn(-2.0f, s[j], xn), g_cnorm[codes[j]]);
                    if (v < bv || (v == bv && codes[j] < bi)) { bv = v; bi = codes[j]; }
                }
            }
        }
        if (lane == 0) g_bmu[row] = bi;
    }
}

// ---------------------------------------------------------------------------
// K2: gather smoothed[bmu] -> output, float4 vectorized (d%4==0 aligned)
// ---------------------------------------------------------------------------
__global__ void k_output(float* __restrict__ out) {
    int e = blockIdx.x * blockDim.x + threadIdx.x;   // one float4 per thread
    int idx = e * 4;
    int w = idx & 63;
    int h = (idx >> 6) & 63;
    int c = (idx >> 12) & 15;
    int n = idx >> 16;
    int i = (n << 8) + ((h >> 2) << 4) + (w >> 2);
    int d = (c << 4) + ((h & 3) << 2);               // w&3 spans the float4
    float4 v = *(const float4*)&g_smooth[g_bmu[i] * DDIM + d];
    *(float4*)&out[idx] = v;
}

// ---------------------------------------------------------------------------
extern "C" void kernel_launch(void* const* d_in, const int* in_sizes, int n_in,
                              void* d_out, int out_size) {
    const float* x  = (const float*)d_in[0];   // (128,16,64,64)
    const float* cb = (const float*)d_in[1];   // (1024,256)
    float* out = (float*)d_out;

    cudaFuncSetAttribute(k_prune, cudaFuncAttributeMaxDynamicSharedMemorySize,
                         SM_TOTAL);

    k_prep  <<<128 + 256, 256>>>(cb);
    k_prune <<<NPATCH / 128, 256, SM_TOTAL>>>(x, cb);
    k_output<<<NPATCH * DDIM / 1024, 256>>>(out);
}